// round 1
// baseline (speedup 1.0000x reference)
#include <cuda_runtime.h>

#define NTOK 2048
#define DIM  512
#define NMOM 25            // polynomial degree 24 (j = 0..24)
#define NCOEF (2*NMOM)     // numerator + denominator coefficients per token

// Scratch (device globals: allocation-free, graph-capture safe)
__device__ float g_Q[NTOK*DIM];
__device__ float g_K[NTOK*DIM];
__device__ float g_V[NTOK*DIM];
__device__ float g_O[NTOK*DIM];
__device__ float g_C[NTOK*NCOEF];

// ---------------------------------------------------------------------------
// SGEMM (NT): C[m,n] = sum_k A[m,k] * B[n,k].  A:[M,512], B:[512,512] row-major.
// 128x128 tile, BK=8, 256 threads, 8x8 microtile per thread.
// ---------------------------------------------------------------------------
__device__ __forceinline__ void sgemm_nt(const float* __restrict__ A,
                                         const float* __restrict__ B,
                                         float* __restrict__ C,
                                         int mBase, int nBase)
{
    __shared__ float As[8][132];   // [kk][m], pad 132 -> conflict-free STS/LDS
    __shared__ float Bs[8][132];   // [kk][n]

    const int tid = threadIdx.x;
    const int tx  = tid & 15;      // 0..15  (n direction)
    const int ty  = tid >> 4;      // 0..15  (m direction)
    const int lr  = tid >> 1;      // load row 0..127
    const int lc  = (tid & 1) * 4; // load col 0 or 4

    float acc[8][8];
#pragma unroll
    for (int i = 0; i < 8; i++)
#pragma unroll
        for (int j = 0; j < 8; j++) acc[i][j] = 0.f;

    const float* Ap = A + (size_t)(mBase + lr) * DIM + lc;
    const float* Bp = B + (size_t)(nBase + lr) * DIM + lc;

    for (int k0 = 0; k0 < DIM; k0 += 8) {
        const float4 av = *(const float4*)(Ap + k0);
        const float4 bv = *(const float4*)(Bp + k0);
        __syncthreads();
        As[lc+0][lr] = av.x; As[lc+1][lr] = av.y; As[lc+2][lr] = av.z; As[lc+3][lr] = av.w;
        Bs[lc+0][lr] = bv.x; Bs[lc+1][lr] = bv.y; Bs[lc+2][lr] = bv.z; Bs[lc+3][lr] = bv.w;
        __syncthreads();
#pragma unroll
        for (int kk = 0; kk < 8; kk++) {
            float a[8], b[8];
            *(float4*)(a)   = *(const float4*)(&As[kk][ty*8]);
            *(float4*)(a+4) = *(const float4*)(&As[kk][ty*8+4]);
            *(float4*)(b)   = *(const float4*)(&Bs[kk][tx*8]);
            *(float4*)(b+4) = *(const float4*)(&Bs[kk][tx*8+4]);
#pragma unroll
            for (int i = 0; i < 8; i++)
#pragma unroll
                for (int j = 0; j < 8; j++)
                    acc[i][j] = fmaf(a[i], b[j], acc[i][j]);
        }
    }

#pragma unroll
    for (int i = 0; i < 8; i++) {
        float* Cr = C + (size_t)(mBase + ty*8 + i) * DIM + nBase + tx*8;
        *(float4*)(Cr)   = make_float4(acc[i][0], acc[i][1], acc[i][2], acc[i][3]);
        *(float4*)(Cr+4) = make_float4(acc[i][4], acc[i][5], acc[i][6], acc[i][7]);
    }
}

// Fused QKV projection: grid.x = 12 (3 matrices x 4 column blocks), grid.y = 16.
__global__ void __launch_bounds__(256)
qkv_gemm(const float* __restrict__ h,
         const float* __restrict__ wq,
         const float* __restrict__ wk,
         const float* __restrict__ wv)
{
    const int cb    = blockIdx.x;
    const int which = cb >> 2;
    const float* B  = (which == 0) ? wq : (which == 1) ? wk : wv;
    float*       C  = (which == 0) ? g_Q : (which == 1) ? g_K : g_V;
    sgemm_nt(h, B, C, blockIdx.y * 128, (cb & 3) * 128);
}

// Output projection: out = O @ W_O^T. grid = (4, 16).
__global__ void __launch_bounds__(256)
out_gemm(const float* __restrict__ wo, float* __restrict__ out)
{
    sgemm_nt(g_O, wo, out, blockIdx.y * 128, blockIdx.x * 128);
}

// ---------------------------------------------------------------------------
// Moments: per token n, coefficients of the Taylor series of
//   num(c) = sum_b v_b e^{c k_b},  den(c) = sum_b e^{c k_b}
// g_C[n][j]      = (sum_b k_b^j v_b) / j!   (j = 0..24)
// g_C[n][25 + j] = (sum_b k_b^j)     / j!
// One warp per token.
// ---------------------------------------------------------------------------
__global__ void __launch_bounds__(256)
moments_kernel()
{
    const int warp = (blockIdx.x * blockDim.x + threadIdx.x) >> 5;
    const int lane = threadIdx.x & 31;
    if (warp >= NTOK) return;

    const float* kp = g_K + (size_t)warp * DIM;
    const float* vp = g_V + (size_t)warp * DIM;

    float um[NMOM], mm[NMOM];
#pragma unroll
    for (int j = 0; j < NMOM; j++) { um[j] = 0.f; mm[j] = 0.f; }

    for (int b = lane; b < DIM; b += 32) {
        const float kb = kp[b];
        const float vb = vp[b];
        float p = 1.f;
#pragma unroll
        for (int j = 0; j < NMOM; j++) {
            mm[j] += p;
            um[j] = fmaf(p, vb, um[j]);
            p *= kb;
        }
    }

#pragma unroll
    for (int j = 0; j < NMOM; j++) {
#pragma unroll
        for (int off = 16; off > 0; off >>= 1) {
            mm[j] += __shfl_xor_sync(0xFFFFFFFFu, mm[j], off);
            um[j] += __shfl_xor_sync(0xFFFFFFFFu, um[j], off);
        }
    }

    if (lane == 0) {
        float fact = 1.f;
        float* dst = g_C + (size_t)warp * NCOEF;
#pragma unroll
        for (int j = 0; j < NMOM; j++) {
            if (j > 0) fact *= (float)j;
            const float inv = 1.0f / fact;
            dst[j]        = um[j] * inv;
            dst[NMOM + j] = mm[j] * inv;
        }
    }
}

// ---------------------------------------------------------------------------
// Pointwise: o[n,a] = num(c)/den(c), c = q[n,a]/sqrt(512). Block per token.
// ---------------------------------------------------------------------------
__global__ void __launch_bounds__(512)
apply_kernel()
{
    const int n = blockIdx.x;
    __shared__ float s[NCOEF];
    if (threadIdx.x < NCOEF) s[threadIdx.x] = g_C[(size_t)n * NCOEF + threadIdx.x];
    __syncthreads();

    const float c = g_Q[(size_t)n * DIM + threadIdx.x] * 0.04419417382415922f; // 1/sqrt(512)

    float num = s[NMOM - 1];
    float den = s[NCOEF - 1];
#pragma unroll
    for (int j = NMOM - 2; j >= 0; j--) {
        num = fmaf(num, c, s[j]);
        den = fmaf(den, c, s[NMOM + j]);
    }
    g_O[(size_t)n * DIM + threadIdx.x] = num / den;
}

// ---------------------------------------------------------------------------
extern "C" void kernel_launch(void* const* d_in, const int* in_sizes, int n_in,
                              void* d_out, int out_size)
{
    const float* h  = (const float*)d_in[0];
    const float* wq = (const float*)d_in[1];
    const float* wk = (const float*)d_in[2];
    const float* wv = (const float*)d_in[3];
    const float* wo = (const float*)d_in[4];
    float* out = (float*)d_out;

    qkv_gemm<<<dim3(12, 16), 256>>>(h, wq, wk, wv);
    moments_kernel<<<256, 256>>>();
    apply_kernel<<<NTOK, 512>>>();
    out_gemm<<<dim3(4, 16), 256>>>(wo, out);
}

// round 3
// speedup vs baseline: 1.8741x; 1.8741x over previous
#include <cuda_runtime.h>
#include <cuda_bf16.h>
#include <cstdint>

#define NTOK 2048
#define DIM  512
#define KP   1536              // packed K' = 3 * DIM (hi/lo split folded into K)
#define NMOM 25
#define NCOEF (2*NMOM)

// ---------------- scratch (device globals: allocation-free) ----------------
__device__ __nv_bfloat16 g_hp [NTOK*KP];   // A-pattern: [Ah | Al | Ah]
__device__ __nv_bfloat16 g_Op [NTOK*KP];   // A-pattern
__device__ __nv_bfloat16 g_wqp[DIM*KP];    // B-pattern: [Bh | Bh | Bl]
__device__ __nv_bfloat16 g_wkp[DIM*KP];
__device__ __nv_bfloat16 g_wvp[DIM*KP];
__device__ __nv_bfloat16 g_wop[DIM*KP];
__device__ float g_Q[NTOK*DIM], g_K[NTOK*DIM], g_V[NTOK*DIM];
__device__ float g_C[NTOK*NCOEF];

// ---------------- PTX helpers ----------------
__device__ __forceinline__ uint32_t smem_u32(const void* p) {
    uint32_t a;
    asm("{ .reg .u64 t; cvta.to.shared.u64 t, %1; cvt.u32.u64 %0, t; }" : "=r"(a) : "l"(p));
    return a;
}
__device__ __forceinline__ void cpa16(uint32_t sdst, const void* gsrc) {
    asm volatile("cp.async.cg.shared.global [%0], [%1], 16;\n" :: "r"(sdst), "l"(gsrc));
}
#define CP_COMMIT() asm volatile("cp.async.commit_group;\n" ::: "memory")
#define CP_WAIT(n)  asm volatile("cp.async.wait_group %0;\n" :: "n"(n) : "memory")

__device__ __forceinline__ void ldsm4(uint32_t* r, uint32_t addr) {
    asm volatile("ldmatrix.sync.aligned.m8n8.x4.shared.b16 {%0,%1,%2,%3}, [%4];"
        : "=r"(r[0]), "=r"(r[1]), "=r"(r[2]), "=r"(r[3]) : "r"(addr));
}
__device__ __forceinline__ void mma_bf16(float* c, const uint32_t* a,
                                         uint32_t b0, uint32_t b1) {
    asm volatile(
        "mma.sync.aligned.m16n8k16.row.col.f32.bf16.bf16.f32 "
        "{%0,%1,%2,%3}, {%4,%5,%6,%7}, {%8,%9}, {%0,%1,%2,%3};"
        : "+f"(c[0]), "+f"(c[1]), "+f"(c[2]), "+f"(c[3])
        : "r"(a[0]), "r"(a[1]), "r"(a[2]), "r"(a[3]), "r"(b0), "r"(b1));
}

// ---------------------------------------------------------------------------
// bf16 GEMM: C[m,n] = sum_k A[m,k]*B[n,k], A:[*,KP], B:[512,KP], K = KP = 1536.
// 128x128 tile, BK=32, 256 threads, warp grid 2(m) x 4(n), warp tile 64x32.
// SMEM stage: A 128x32 bf16 (8KB) + B 128x32 (8KB); double buffered (32KB).
// 64B rows, 16B units swizzled: u' = u ^ (row & 3)  -> conflict-free ldmatrix.
// ---------------------------------------------------------------------------
#define BK     32
#define NITER  (KP / BK)       // 48
#define STG_B  16384

__device__ __forceinline__ void gemm_fill(uint32_t sb, int stage,
                                          const __nv_bfloat16* A, int mBase,
                                          const __nv_bfloat16* B, int nBase,
                                          int k0, int tid)
{
    const uint32_t base = sb + stage * STG_B;
#pragma unroll
    for (int half = 0; half < 2; half++) {
        const int c = tid + half * 256;          // 0..511
        const int r = c >> 2, u = c & 3;
        const uint32_t dst = base + r * 64 + ((u ^ (r & 3)) * 16);
        cpa16(dst,       A + (size_t)(mBase + r) * KP + k0 + u * 8);
        cpa16(dst + 8192, B + (size_t)(nBase + r) * KP + k0 + u * 8);
    }
}

__device__ void gemm_tile(const __nv_bfloat16* __restrict__ A,
                          const __nv_bfloat16* __restrict__ B,
                          float* __restrict__ C,
                          int mBase, int nBase)
{
    __shared__ __align__(1024) char smem[2 * STG_B];
    const uint32_t sb = smem_u32(smem);
    const int tid  = threadIdx.x;
    const int lane = tid & 31;
    const int wid  = tid >> 5;
    const int wm   = wid >> 2;          // 0..1
    const int wn   = wid & 3;           // 0..3

    float acc[4][4][4];
#pragma unroll
    for (int i = 0; i < 4; i++)
#pragma unroll
        for (int j = 0; j < 4; j++)
#pragma unroll
            for (int q = 0; q < 4; q++) acc[i][j][q] = 0.f;

    gemm_fill(sb, 0, A, mBase, B, nBase, 0, tid);
    CP_COMMIT();

    const int lrow = lane & 15;
    const int lhi  = lane >> 4;         // 0: k-lo half, 1: k-hi half

    for (int it = 0; it < NITER; ++it) {
        if (it + 1 < NITER) {
            gemm_fill(sb, (it + 1) & 1, A, mBase, B, nBase, (it + 1) * BK, tid);
            CP_COMMIT();
            CP_WAIT(1);
        } else {
            CP_WAIT(0);
        }
        __syncthreads();

        const uint32_t base = sb + (it & 1) * STG_B;
#pragma unroll
        for (int ks = 0; ks < 2; ks++) {
            const int u = ks * 2 + lhi;
            uint32_t a[4][4], b[2][4];
#pragma unroll
            for (int mt = 0; mt < 4; mt++) {
                const int r = wm * 64 + mt * 16 + lrow;
                ldsm4(a[mt], base + r * 64 + ((u ^ (r & 3)) * 16));
            }
#pragma unroll
            for (int bt = 0; bt < 2; bt++) {
                const int r = wn * 32 + bt * 16 + lrow;
                ldsm4(b[bt], base + 8192 + r * 64 + ((u ^ (r & 3)) * 16));
            }
#pragma unroll
            for (int mt = 0; mt < 4; mt++)
#pragma unroll
                for (int nt = 0; nt < 4; nt++) {
                    const uint32_t b0 = (nt & 1) ? b[nt >> 1][1] : b[nt >> 1][0];
                    const uint32_t b1 = (nt & 1) ? b[nt >> 1][3] : b[nt >> 1][2];
                    mma_bf16(acc[mt][nt], a[mt], b0, b1);
                }
        }
        __syncthreads();
    }

    const int crow = mBase + wm * 64 + (lane >> 2);
    const int ccol = nBase + wn * 32 + (lane & 3) * 2;
#pragma unroll
    for (int mt = 0; mt < 4; mt++)
#pragma unroll
        for (int nt = 0; nt < 4; nt++) {
            float* p0 = C + (size_t)(crow + mt * 16) * DIM + ccol + nt * 8;
            float* p1 = p0 + 8 * DIM;
            *(float2*)p0 = make_float2(acc[mt][nt][0], acc[mt][nt][1]);
            *(float2*)p1 = make_float2(acc[mt][nt][2], acc[mt][nt][3]);
        }
}

__global__ void __launch_bounds__(256, 2)
qkv_gemm()
{
    const int which = blockIdx.x >> 2;
    const __nv_bfloat16* B = (which == 0) ? g_wqp : (which == 1) ? g_wkp : g_wvp;
    float* C               = (which == 0) ? g_Q   : (which == 1) ? g_K   : g_V;
    gemm_tile(g_hp, B, C, blockIdx.y * 128, (blockIdx.x & 3) * 128);
}

__global__ void __launch_bounds__(256, 2)
out_gemm(float* __restrict__ out)
{
    gemm_tile(g_Op, g_wop, out, blockIdx.y * 128, blockIdx.x * 128);
}

// ---------------- fp32 -> packed bf16 hi/lo split ---------------------------
// A-pattern (h):   dst[r][k]=hi, dst[r][512+k]=lo, dst[r][1024+k]=hi
// B-pattern (W):   dst[r][k]=hi, dst[r][512+k]=hi, dst[r][1024+k]=lo
__global__ void __launch_bounds__(256)
split_kernel(const float* __restrict__ h,  const float* __restrict__ wq,
             const float* __restrict__ wk, const float* __restrict__ wv,
             const float* __restrict__ wo)
{
    const int i = blockIdx.x * 256 + threadIdx.x;
    const float* src; __nv_bfloat16* dst; int off; bool patA;
    if (i < NTOK * DIM) { src = h; dst = g_hp; off = i; patA = true; }
    else {
        const int j = i - NTOK * DIM;
        const int w = j >> 18;
        off = j & ((1 << 18) - 1);
        patA = false;
        if (w == 0)      { src = wq; dst = g_wqp; }
        else if (w == 1) { src = wk; dst = g_wkp; }
        else if (w == 2) { src = wv; dst = g_wvp; }
        else             { src = wo; dst = g_wop; }
    }
    const int r = off >> 9, k = off & 511;
    const float x = src[off];
    const __nv_bfloat16 hi = __float2bfloat16(x);
    const __nv_bfloat16 lo = __float2bfloat16(x - __bfloat162float(hi));
    __nv_bfloat16* row = dst + (size_t)r * KP + k;
    row[0]    = hi;
    row[512]  = patA ? lo : hi;
    row[1024] = patA ? hi : lo;
}

// ---------------- moments: Taylor coefficients per token --------------------
__global__ void __launch_bounds__(256)
moments_kernel()
{
    const int warp = (blockIdx.x * blockDim.x + threadIdx.x) >> 5;
    const int lane = threadIdx.x & 31;
    if (warp >= NTOK) return;
    const float* kp = g_K + (size_t)warp * DIM;
    const float* vp = g_V + (size_t)warp * DIM;
    float um[NMOM], mm[NMOM];
#pragma unroll
    for (int j = 0; j < NMOM; j++) { um[j] = 0.f; mm[j] = 0.f; }
    for (int b = lane; b < DIM; b += 32) {
        const float kb = kp[b], vb = vp[b];
        float p = 1.f;
#pragma unroll
        for (int j = 0; j < NMOM; j++) {
            mm[j] += p;
            um[j] = fmaf(p, vb, um[j]);
            p *= kb;
        }
    }
#pragma unroll
    for (int j = 0; j < NMOM; j++)
#pragma unroll
        for (int off = 16; off > 0; off >>= 1) {
            mm[j] += __shfl_xor_sync(0xFFFFFFFFu, mm[j], off);
            um[j] += __shfl_xor_sync(0xFFFFFFFFu, um[j], off);
        }
    if (lane == 0) {
        float fact = 1.f;
        float* dst = g_C + (size_t)warp * NCOEF;
#pragma unroll
        for (int j = 0; j < NMOM; j++) {
            if (j > 0) fact *= (float)j;
            const float inv = 1.0f / fact;
            dst[j]        = um[j] * inv;
            dst[NMOM + j] = mm[j] * inv;
        }
    }
}

// ---------------- apply: o = num(c)/den(c); emit packed bf16 (A-pattern) ----
__global__ void __launch_bounds__(512)
apply_kernel()
{
    const int n = blockIdx.x;
    __shared__ float s[NCOEF];
    if (threadIdx.x < NCOEF) s[threadIdx.x] = g_C[(size_t)n * NCOEF + threadIdx.x];
    __syncthreads();
    const float c = g_Q[(size_t)n * DIM + threadIdx.x] * 0.04419417382415922f;
    float num = s[NMOM - 1], den = s[NCOEF - 1];
#pragma unroll
    for (int j = NMOM - 2; j >= 0; j--) {
        num = fmaf(num, c, s[j]);
        den = fmaf(den, c, s[NMOM + j]);
    }
    const float o = num / den;
    const __nv_bfloat16 hi = __float2bfloat16(o);
    const __nv_bfloat16 lo = __float2bfloat16(o - __bfloat162float(hi));
    __nv_bfloat16* row = g_Op + (size_t)n * KP + threadIdx.x;
    row[0]    = hi;
    row[512]  = lo;
    row[1024] = hi;
}

// ---------------------------------------------------------------------------
extern "C" void kernel_launch(void* const* d_in, const int* in_sizes, int n_in,
                              void* d_out, int out_size)
{
    const float* h  = (const float*)d_in[0];
    const float* wq = (const float*)d_in[1];
    const float* wk = (const float*)d_in[2];
    const float* wv = (const float*)d_in[3];
    const float* wo = (const float*)d_in[4];
    float* out = (float*)d_out;

    split_kernel<<<(NTOK * DIM + 4 * DIM * DIM) / 256, 256>>>(h, wq, wk, wv, wo);
    qkv_gemm<<<dim3(12, 16), 256>>>();
    moments_kernel<<<256, 256>>>();
    apply_kernel<<<NTOK, 512>>>();
    out_gemm<<<dim3(4, 16), 256>>>(out);
}

// round 4
// speedup vs baseline: 2.4749x; 1.3206x over previous
#include <cuda_runtime.h>
#include <cuda_bf16.h>
#include <cstdint>

#define NTOK 2048
#define DIM  512
#define KP   1536              // packed K' = 3 * DIM (hi/lo split folded into K)
#define NMOM 25
#define NCOEF (2*NMOM)

// ---------------- scratch (device globals: allocation-free) ----------------
__device__ __nv_bfloat16 g_hp [NTOK*KP];   // A-pattern: [Ah | Al | Ah]
__device__ __nv_bfloat16 g_Op [NTOK*KP];   // A-pattern
__device__ __nv_bfloat16 g_wqh[DIM*DIM];   // W_Q hi only (1-term Q projection)
__device__ __nv_bfloat16 g_wkp[DIM*KP];    // B-pattern: [Bh | Bh | Bl]
__device__ __nv_bfloat16 g_wvp[DIM*KP];
__device__ __nv_bfloat16 g_wop[DIM*KP];
__device__ float g_Q[NTOK*DIM], g_K[NTOK*DIM], g_V[NTOK*DIM];
__device__ float g_C[NTOK*NCOEF];

// ---------------- PTX helpers ----------------
__device__ __forceinline__ uint32_t smem_u32(const void* p) {
    uint32_t a;
    asm("{ .reg .u64 t; cvta.to.shared.u64 t, %1; cvt.u32.u64 %0, t; }" : "=r"(a) : "l"(p));
    return a;
}
__device__ __forceinline__ void cpa16(uint32_t sdst, const void* gsrc) {
    asm volatile("cp.async.cg.shared.global [%0], [%1], 16;\n" :: "r"(sdst), "l"(gsrc));
}
#define CP_COMMIT() asm volatile("cp.async.commit_group;\n" ::: "memory")
#define CP_WAIT(n)  asm volatile("cp.async.wait_group %0;\n" :: "n"(n) : "memory")

__device__ __forceinline__ void ldsm4(uint32_t* r, uint32_t addr) {
    asm volatile("ldmatrix.sync.aligned.m8n8.x4.shared.b16 {%0,%1,%2,%3}, [%4];"
        : "=r"(r[0]), "=r"(r[1]), "=r"(r[2]), "=r"(r[3]) : "r"(addr));
}
__device__ __forceinline__ void mma_bf16(float* c, const uint32_t* a,
                                         uint32_t b0, uint32_t b1) {
    asm volatile(
        "mma.sync.aligned.m16n8k16.row.col.f32.bf16.bf16.f32 "
        "{%0,%1,%2,%3}, {%4,%5,%6,%7}, {%8,%9}, {%0,%1,%2,%3};"
        : "+f"(c[0]), "+f"(c[1]), "+f"(c[2]), "+f"(c[3])
        : "r"(a[0]), "r"(a[1]), "r"(a[2]), "r"(a[3]), "r"(b0), "r"(b1));
}

// ---------------------------------------------------------------------------
// bf16 GEMM: C[m,n] = sum_k A[m,k]*B[n,k].  M-tile 128, N-tile BN (128 or 64),
// BK=64, 256 threads, warp grid 2(m) x 4(n).  2-stage cp.async pipeline,
// ONE __syncthreads per k-iter.  128B smem rows, 16B-unit xor swizzle.
// ---------------------------------------------------------------------------
template<int BN>
__device__ __forceinline__ void gemm_fill(uint32_t base,
    const __nv_bfloat16* A, int lda, int mBase,
    const __nv_bfloat16* B, int ldb, int nBase, int k0, int tid)
{
#pragma unroll
    for (int i = 0; i < 4; i++) {                       // A: 128 rows x 8 units
        const int idx = i * 256 + tid;
        const int r = idx >> 3, u = idx & 7;
        cpa16(base + r * 128 + ((u ^ (r & 7)) << 4),
              A + (size_t)(mBase + r) * lda + k0 + u * 8);
    }
#pragma unroll
    for (int i = 0; i < BN / 32; i++) {                 // B: BN rows x 8 units
        const int idx = i * 256 + tid;
        const int r = idx >> 3, u = idx & 7;
        cpa16(base + 16384 + r * 128 + ((u ^ (r & 7)) << 4),
              B + (size_t)(nBase + r) * ldb + k0 + u * 8);
    }
}

template<int BN>
__device__ void gemm_tile(const __nv_bfloat16* __restrict__ A, int lda,
                          const __nv_bfloat16* __restrict__ B, int ldb,
                          float* __restrict__ C,
                          int mBase, int nBase, int kIters)
{
    constexpr int BT  = BN / 64;      // ldsm b-groups per warp (16 rows each)
    constexpr int NTT = BN / 32;      // 8-wide n subtiles per warp
    constexpr int STG = 16384 + BN * 128;

    extern __shared__ __align__(1024) char smem[];
    const uint32_t sb = smem_u32(smem);
    const int tid = threadIdx.x, lane = tid & 31, wid = tid >> 5;
    const int wm = wid >> 2, wn = wid & 3;

    float acc[4][NTT][4];
#pragma unroll
    for (int i = 0; i < 4; i++)
#pragma unroll
        for (int j = 0; j < NTT; j++)
#pragma unroll
            for (int q = 0; q < 4; q++) acc[i][j][q] = 0.f;

    gemm_fill<BN>(sb, A, lda, mBase, B, ldb, nBase, 0, tid);
    CP_COMMIT();

    const int lrow = lane & 15, lhi = lane >> 4;

    for (int it = 0; it < kIters; ++it) {
        CP_WAIT(0);
        __syncthreads();
        if (it + 1 < kIters) {
            gemm_fill<BN>(sb + ((it + 1) & 1) * STG, A, lda, mBase,
                          B, ldb, nBase, (it + 1) * 64, tid);
            CP_COMMIT();
        }
        const uint32_t base = sb + (it & 1) * STG;
#pragma unroll
        for (int ks = 0; ks < 4; ks++) {
            const int u = ks * 2 + lhi;
            uint32_t a[4][4], b[BT][4];
#pragma unroll
            for (int mt = 0; mt < 4; mt++) {
                const int r = wm * 64 + mt * 16 + lrow;
                ldsm4(a[mt], base + r * 128 + ((u ^ (r & 7)) << 4));
            }
#pragma unroll
            for (int bt = 0; bt < BT; bt++) {
                const int r = wn * (BN / 4) + bt * 16 + lrow;
                ldsm4(b[bt], base + 16384 + r * 128 + ((u ^ (r & 7)) << 4));
            }
#pragma unroll
            for (int mt = 0; mt < 4; mt++)
#pragma unroll
                for (int nt = 0; nt < NTT; nt++) {
                    const uint32_t b0 = (nt & 1) ? b[nt >> 1][1] : b[nt >> 1][0];
                    const uint32_t b1 = (nt & 1) ? b[nt >> 1][3] : b[nt >> 1][2];
                    mma_bf16(acc[mt][nt], a[mt], b0, b1);
                }
        }
    }

    const int crow = mBase + wm * 64 + (lane >> 2);
    const int ccol = nBase + wn * (BN / 4) + (lane & 3) * 2;
#pragma unroll
    for (int mt = 0; mt < 4; mt++)
#pragma unroll
        for (int nt = 0; nt < NTT; nt++) {
            float* p0 = C + (size_t)(crow + mt * 16) * DIM + ccol + nt * 8;
            float* p1 = p0 + 8 * DIM;
            *(float2*)p0 = make_float2(acc[mt][nt][0], acc[mt][nt][1]);
            *(float2*)p1 = make_float2(acc[mt][nt][2], acc[mt][nt][3]);
        }
}

__global__ void __launch_bounds__(256, 2)
qkv_gemm()
{
    const int which = blockIdx.x >> 2;
    const int nBase = (blockIdx.x & 3) * 128;
    const int mBase = blockIdx.y * 128;
    if (which == 0)
        gemm_tile<128>(g_hp, KP, g_wqh, DIM, g_Q, mBase, nBase, 8);   // 1-term Q
    else if (which == 1)
        gemm_tile<128>(g_hp, KP, g_wkp, KP, g_K, mBase, nBase, 24);
    else
        gemm_tile<128>(g_hp, KP, g_wvp, KP, g_V, mBase, nBase, 24);
}

__global__ void __launch_bounds__(256, 2)
out_gemm(float* __restrict__ out)
{
    gemm_tile<64>(g_Op, KP, g_wop, KP, out, blockIdx.y * 128, blockIdx.x * 64, 24);
}

// ---------------- fp32 -> packed bf16 hi/lo split ---------------------------
__global__ void __launch_bounds__(256)
split_kernel(const float* __restrict__ h,  const float* __restrict__ wq,
             const float* __restrict__ wk, const float* __restrict__ wv,
             const float* __restrict__ wo)
{
    const int i = blockIdx.x * 256 + threadIdx.x;
    if (i < NTOK * DIM) {                       // h: A-pattern [hi|lo|hi]
        const int r = i >> 9, k = i & 511;
        const float x = h[i];
        const __nv_bfloat16 hi = __float2bfloat16(x);
        const __nv_bfloat16 lo = __float2bfloat16(x - __bfloat162float(hi));
        __nv_bfloat16* row = g_hp + (size_t)r * KP + k;
        row[0] = hi; row[512] = lo; row[1024] = hi;
        return;
    }
    const int j = i - NTOK * DIM;
    const int w = j >> 18;
    const int off = j & ((1 << 18) - 1);
    if (w == 0) {                               // W_Q: hi only
        g_wqh[off] = __float2bfloat16(wq[off]);
        return;
    }
    const float* src = (w == 1) ? wk : (w == 2) ? wv : wo;
    __nv_bfloat16* dst = (w == 1) ? g_wkp : (w == 2) ? g_wvp : g_wop;
    const int r = off >> 9, k = off & 511;
    const float x = src[off];
    const __nv_bfloat16 hi = __float2bfloat16(x);
    const __nv_bfloat16 lo = __float2bfloat16(x - __bfloat162float(hi));
    __nv_bfloat16* row = dst + (size_t)r * KP + k;                 // B-pattern
    row[0] = hi; row[512] = hi; row[1024] = lo;
}

// ---------------- moments: Taylor coefficients per token --------------------
__global__ void __launch_bounds__(256)
moments_kernel()
{
    const int warp = (blockIdx.x * blockDim.x + threadIdx.x) >> 5;
    const int lane = threadIdx.x & 31;
    if (warp >= NTOK) return;
    const float* kp = g_K + (size_t)warp * DIM;
    const float* vp = g_V + (size_t)warp * DIM;
    float um[NMOM], mm[NMOM];
#pragma unroll
    for (int j = 0; j < NMOM; j++) { um[j] = 0.f; mm[j] = 0.f; }
    for (int b = lane; b < DIM; b += 32) {
        const float kb = kp[b], vb = vp[b];
        float p = 1.f;
#pragma unroll
        for (int j = 0; j < NMOM; j++) {
            mm[j] += p;
            um[j] = fmaf(p, vb, um[j]);
            p *= kb;
        }
    }
#pragma unroll
    for (int j = 0; j < NMOM; j++)
#pragma unroll
        for (int off = 16; off > 0; off >>= 1) {
            mm[j] += __shfl_xor_sync(0xFFFFFFFFu, mm[j], off);
            um[j] += __shfl_xor_sync(0xFFFFFFFFu, um[j], off);
        }
    if (lane == 0) {
        float fact = 1.f;
        float* dst = g_C + (size_t)warp * NCOEF;
#pragma unroll
        for (int j = 0; j < NMOM; j++) {
            if (j > 0) fact *= (float)j;
            const float inv = 1.0f / fact;
            dst[j]        = um[j] * inv;
            dst[NMOM + j] = mm[j] * inv;
        }
    }
}

// ---------------- apply: o = num(c)/den(c); 2 outputs/thread ----------------
__global__ void __launch_bounds__(256)
apply_kernel()
{
    const int n = blockIdx.x;
    __shared__ float s[NCOEF];
    if (threadIdx.x < NCOEF) s[threadIdx.x] = g_C[(size_t)n * NCOEF + threadIdx.x];
    __syncthreads();

    const int a0 = threadIdx.x, a1 = threadIdx.x + 256;
    const float c0 = g_Q[(size_t)n * DIM + a0] * 0.04419417382415922f;
    const float c1 = g_Q[(size_t)n * DIM + a1] * 0.04419417382415922f;

    float n0 = s[NMOM - 1], d0 = s[NCOEF - 1];
    float n1 = n0,          d1 = d0;
#pragma unroll
    for (int j = NMOM - 2; j >= 0; j--) {
        const float cu = s[j], cd = s[NMOM + j];
        n0 = fmaf(n0, c0, cu);  d0 = fmaf(d0, c0, cd);
        n1 = fmaf(n1, c1, cu);  d1 = fmaf(d1, c1, cd);
    }
    const float o0 = n0 / d0, o1 = n1 / d1;

    __nv_bfloat16* r0 = g_Op + (size_t)n * KP + a0;
    __nv_bfloat16* r1 = g_Op + (size_t)n * KP + a1;
    const __nv_bfloat16 h0 = __float2bfloat16(o0);
    const __nv_bfloat16 l0 = __float2bfloat16(o0 - __bfloat162float(h0));
    const __nv_bfloat16 h1 = __float2bfloat16(o1);
    const __nv_bfloat16 l1 = __float2bfloat16(o1 - __bfloat162float(h1));
    r0[0] = h0; r0[512] = l0; r0[1024] = h0;
    r1[0] = h1; r1[512] = l1; r1[1024] = h1;
}

// ---------------------------------------------------------------------------
extern "C" void kernel_launch(void* const* d_in, const int* in_sizes, int n_in,
                              void* d_out, int out_size)
{
    const float* h  = (const float*)d_in[0];
    const float* wq = (const float*)d_in[1];
    const float* wk = (const float*)d_in[2];
    const float* wv = (const float*)d_in[3];
    const float* wo = (const float*)d_in[4];
    float* out = (float*)d_out;

    static int attr_done = 0;
    if (!attr_done) {
        cudaFuncSetAttribute(qkv_gemm, cudaFuncAttributeMaxDynamicSharedMemorySize, 65536);
        cudaFuncSetAttribute(out_gemm, cudaFuncAttributeMaxDynamicSharedMemorySize, 49152);
        attr_done = 1;
    }

    split_kernel<<<(NTOK * DIM + 4 * DIM * DIM) / 256, 256>>>(h, wq, wk, wv, wo);
    qkv_gemm<<<dim3(12, 16), 256, 65536>>>();
    moments_kernel<<<256, 256>>>();
    apply_kernel<<<NTOK, 256>>>();
    out_gemm<<<dim3(8, 16), 256, 49152>>>(out);
}

// round 5
// speedup vs baseline: 3.3316x; 1.3462x over previous
#include <cuda_runtime.h>
#include <cuda_bf16.h>
#include <cstdint>

#define NTOK 2048
#define DIM  512
#define LDP  1024              // packed 2-segment leading dim [hi|lo]
#define NMOM 15
#define NCOEF (2*NMOM)

// ---------------- scratch (device globals: allocation-free) ----------------
__device__ __nv_bfloat16 g_hp [NTOK*LDP];    // h:   [Ah | Al]
__device__ __nv_bfloat16 g_Op [NTOK*LDP];    // O:   [Oh | Ol]
__device__ __nv_bfloat16 g_wqh[DIM*DIM];     // W_Q hi only (1-term)
__device__ __nv_bfloat16 g_wkh[DIM*DIM];     // W_K hi only (1-term)
__device__ __nv_bfloat16 g_wvp[DIM*LDP];     // W_V: [Bh | Bl]
__device__ __nv_bfloat16 g_wop[DIM*LDP];     // W_O: [Bh | Bl]
__device__ float g_Q[NTOK*DIM], g_K[NTOK*DIM];
__device__ float g_Vp[3*NTOK*DIM];           // V partial sums (3 segment GEMMs)
__device__ float g_C[NTOK*NCOEF];

// 3-term product via segments: seg s: A k-off {0,512,0}, B k-off {0,0,512}
__device__ __forceinline__ int segA(int s) { return (s == 1) ? 512 : 0; }
__device__ __forceinline__ int segB(int s) { return (s == 2) ? 512 : 0; }

// ---------------- PTX helpers ----------------
__device__ __forceinline__ uint32_t smem_u32(const void* p) {
    uint32_t a;
    asm("{ .reg .u64 t; cvta.to.shared.u64 t, %1; cvt.u32.u64 %0, t; }" : "=r"(a) : "l"(p));
    return a;
}
__device__ __forceinline__ void cpa16(uint32_t sdst, const void* gsrc) {
    asm volatile("cp.async.cg.shared.global [%0], [%1], 16;\n" :: "r"(sdst), "l"(gsrc));
}
#define CP_COMMIT() asm volatile("cp.async.commit_group;\n" ::: "memory")
#define CP_WAIT(n)  asm volatile("cp.async.wait_group %0;\n" :: "n"(n) : "memory")

__device__ __forceinline__ void ldsm4(uint32_t* r, uint32_t addr) {
    asm volatile("ldmatrix.sync.aligned.m8n8.x4.shared.b16 {%0,%1,%2,%3}, [%4];"
        : "=r"(r[0]), "=r"(r[1]), "=r"(r[2]), "=r"(r[3]) : "r"(addr));
}
__device__ __forceinline__ void mma_bf16(float* c, const uint32_t* a,
                                         uint32_t b0, uint32_t b1) {
    asm volatile(
        "mma.sync.aligned.m16n8k16.row.col.f32.bf16.bf16.f32 "
        "{%0,%1,%2,%3}, {%4,%5,%6,%7}, {%8,%9}, {%0,%1,%2,%3};"
        : "+f"(c[0]), "+f"(c[1]), "+f"(c[2]), "+f"(c[3])
        : "r"(a[0]), "r"(a[1]), "r"(a[2]), "r"(a[3]), "r"(b0), "r"(b1));
}

// ---------------------------------------------------------------------------
// bf16 GEMM tile: C[m,n] = sum_k A[m,ka+k]*B[n,kb+k].  BM=128, BN in {64,128},
// BK=64, 256 threads, 2(m) x 4(n) warps, 2-stage cp.async, 1 sync per k-iter.
// SEG=true: k-iters walk 3 segments of 8 iters each (seg offset maps above).
// ---------------------------------------------------------------------------
template<int BN>
__device__ __forceinline__ void gemm_fill(uint32_t base,
    const __nv_bfloat16* A, int lda, int ka,
    const __nv_bfloat16* B, int ldb, int kb, int tid)
{
#pragma unroll
    for (int i = 0; i < 4; i++) {                       // A: 128 rows x 8 units
        const int idx = i * 256 + tid;
        const int r = idx >> 3, u = idx & 7;
        cpa16(base + r * 128 + ((u ^ (r & 7)) << 4),
              A + (size_t)r * lda + ka + u * 8);
    }
#pragma unroll
    for (int i = 0; i < BN / 32; i++) {                 // B: BN rows x 8 units
        const int idx = i * 256 + tid;
        const int r = idx >> 3, u = idx & 7;
        cpa16(base + 16384 + r * 128 + ((u ^ (r & 7)) << 4),
              B + (size_t)r * ldb + kb + u * 8);
    }
}

template<int BN, bool SEG>
__device__ void gemm_tile(const __nv_bfloat16* __restrict__ A, int lda, int k0a,
                          const __nv_bfloat16* __restrict__ B, int ldb, int k0b,
                          float* __restrict__ C,
                          int mBase, int nBase, int kIters)
{
    constexpr int BT  = BN / 64;
    constexpr int NTT = BN / 32;
    constexpr int STG = 16384 + BN * 128;

    extern __shared__ __align__(1024) char smem[];
    const uint32_t sb = smem_u32(smem);
    const int tid = threadIdx.x, lane = tid & 31, wid = tid >> 5;
    const int wm = wid >> 2, wn = wid & 3;

    const __nv_bfloat16* Ab = A + (size_t)mBase * lda;
    const __nv_bfloat16* Bb = B + (size_t)nBase * ldb;

    float acc[4][NTT][4];
#pragma unroll
    for (int i = 0; i < 4; i++)
#pragma unroll
        for (int j = 0; j < NTT; j++)
#pragma unroll
            for (int q = 0; q < 4; q++) acc[i][j][q] = 0.f;

    auto koffs = [&](int it, int& ka, int& kb) {
        if (SEG) {
            const int s = it >> 3, kk = (it & 7) * 64;
            ka = segA(s) + kk; kb = segB(s) + kk;
        } else {
            ka = k0a + it * 64; kb = k0b + it * 64;
        }
    };

    { int ka, kb; koffs(0, ka, kb);
      gemm_fill<BN>(sb, Ab, lda, ka, Bb, ldb, kb, tid); }
    CP_COMMIT();

    const int lrow = lane & 15, lhi = lane >> 4;

    for (int it = 0; it < kIters; ++it) {
        CP_WAIT(0);
        __syncthreads();
        if (it + 1 < kIters) {
            int ka, kb; koffs(it + 1, ka, kb);
            gemm_fill<BN>(sb + ((it + 1) & 1) * STG, Ab, lda, ka, Bb, ldb, kb, tid);
            CP_COMMIT();
        }
        const uint32_t base = sb + (it & 1) * STG;
#pragma unroll
        for (int ks = 0; ks < 4; ks++) {
            const int u = ks * 2 + lhi;
            uint32_t a[4][4], b[BT][4];
#pragma unroll
            for (int mt = 0; mt < 4; mt++) {
                const int r = wm * 64 + mt * 16 + lrow;
                ldsm4(a[mt], base + r * 128 + ((u ^ (r & 7)) << 4));
            }
#pragma unroll
            for (int bt = 0; bt < BT; bt++) {
                const int r = wn * (BN / 4) + bt * 16 + lrow;
                ldsm4(b[bt], base + 16384 + r * 128 + ((u ^ (r & 7)) << 4));
            }
#pragma unroll
            for (int mt = 0; mt < 4; mt++)
#pragma unroll
                for (int nt = 0; nt < NTT; nt++) {
                    const uint32_t b0 = (nt & 1) ? b[nt >> 1][1] : b[nt >> 1][0];
                    const uint32_t b1 = (nt & 1) ? b[nt >> 1][3] : b[nt >> 1][2];
                    mma_bf16(acc[mt][nt], a[mt], b0, b1);
                }
        }
    }

    const int crow = mBase + wm * 64 + (lane >> 2);
    const int ccol = nBase + wn * (BN / 4) + (lane & 3) * 2;
#pragma unroll
    for (int mt = 0; mt < 4; mt++)
#pragma unroll
        for (int nt = 0; nt < NTT; nt++) {
            float* p0 = C + (size_t)(crow + mt * 16) * DIM + ccol + nt * 8;
            float* p1 = p0 + 8 * DIM;
            *(float2*)p0 = make_float2(acc[mt][nt][0], acc[mt][nt][1]);
            *(float2*)p1 = make_float2(acc[mt][nt][2], acc[mt][nt][3]);
        }
}

// Uniform-job QKV: 320 CTAs x 8 k-iters each.
//   [0,64):    Q tiles (1-term)        [64,128): K tiles (1-term)
//   [128,320): V tile x segment s -> partial buffer g_Vp[s]
__global__ void __launch_bounds__(256, 2)
qkv_gemm()
{
    const int j = blockIdx.x;
    if (j < 128) {
        const int q = (j < 64);
        const int t = j & 63;
        gemm_tile<128, false>(g_hp, LDP, 0,
                              q ? g_wqh : g_wkh, DIM, 0,
                              q ? g_Q : g_K,
                              (t >> 2) * 128, (t & 3) * 128, 8);
    } else {
        const int t = j - 128;
        const int s = t / 64, tt = t % 64;
        gemm_tile<128, false>(g_hp, LDP, segA(s),
                              g_wvp, LDP, segB(s),
                              g_Vp + (size_t)s * NTOK * DIM,
                              (tt >> 2) * 128, (tt & 3) * 128, 8);
    }
}

__global__ void __launch_bounds__(256, 2)
out_gemm(float* __restrict__ out)
{
    gemm_tile<64, true>(g_Op, LDP, 0, g_wop, LDP, 0, out,
                        blockIdx.y * 128, blockIdx.x * 64, 24);
}

// ---------------- fp32 -> bf16 hi/lo split ----------------------------------
__global__ void __launch_bounds__(256)
split_kernel(const float* __restrict__ h,  const float* __restrict__ wq,
             const float* __restrict__ wk, const float* __restrict__ wv,
             const float* __restrict__ wo)
{
    const int i = blockIdx.x * 256 + threadIdx.x;
    if (i < NTOK * DIM) {
        const int r = i >> 9, k = i & 511;
        const float x = h[i];
        const __nv_bfloat16 hi = __float2bfloat16(x);
        g_hp[(size_t)r * LDP + k]       = hi;
        g_hp[(size_t)r * LDP + k + 512] = __float2bfloat16(x - __bfloat162float(hi));
        return;
    }
    const int j = i - NTOK * DIM;
    const int w = j >> 18;
    const int off = j & ((1 << 18) - 1);
    if (w == 0) { g_wqh[off] = __float2bfloat16(wq[off]); return; }
    if (w == 1) { g_wkh[off] = __float2bfloat16(wk[off]); return; }
    const float* src = (w == 2) ? wv : wo;
    __nv_bfloat16* dst = (w == 2) ? g_wvp : g_wop;
    const int r = off >> 9, k = off & 511;
    const float x = src[off];
    const __nv_bfloat16 hi = __float2bfloat16(x);
    dst[(size_t)r * LDP + k]       = hi;
    dst[(size_t)r * LDP + k + 512] = __float2bfloat16(x - __bfloat162float(hi));
}

// ---------------- moments: deg-14 Taylor coefficients per token -------------
__global__ void __launch_bounds__(256)
moments_kernel()
{
    const int warp = (blockIdx.x * blockDim.x + threadIdx.x) >> 5;
    const int lane = threadIdx.x & 31;
    if (warp >= NTOK) return;
    const float* kp  = g_K  + (size_t)warp * DIM;
    const float* vp0 = g_Vp + (size_t)warp * DIM;
    const float* vp1 = vp0 + (size_t)NTOK * DIM;
    const float* vp2 = vp1 + (size_t)NTOK * DIM;
    float um[NMOM], mm[NMOM];
#pragma unroll
    for (int j = 0; j < NMOM; j++) { um[j] = 0.f; mm[j] = 0.f; }
    for (int b = lane; b < DIM; b += 32) {
        const float kb = kp[b];
        const float vb = vp0[b] + vp1[b] + vp2[b];
        float p = 1.f;
#pragma unroll
        for (int j = 0; j < NMOM; j++) {
            mm[j] += p;
            um[j] = fmaf(p, vb, um[j]);
            p *= kb;
        }
    }
#pragma unroll
    for (int j = 0; j < NMOM; j++)
#pragma unroll
        for (int off = 16; off > 0; off >>= 1) {
            mm[j] += __shfl_xor_sync(0xFFFFFFFFu, mm[j], off);
            um[j] += __shfl_xor_sync(0xFFFFFFFFu, um[j], off);
        }
    if (lane == 0) {
        float fact = 1.f;
        float* dst = g_C + (size_t)warp * NCOEF;
#pragma unroll
        for (int j = 0; j < NMOM; j++) {
            if (j > 0) fact *= (float)j;
            const float inv = 1.0f / fact;
            dst[j]        = um[j] * inv;
            dst[NMOM + j] = mm[j] * inv;
        }
    }
}

// ---------------- apply: o = num(c)/den(c); write O hi/lo -------------------
__global__ void __launch_bounds__(256)
apply_kernel()
{
    const int n = blockIdx.x;
    __shared__ float s[NCOEF];
    if (threadIdx.x < NCOEF) s[threadIdx.x] = g_C[(size_t)n * NCOEF + threadIdx.x];
    __syncthreads();

    const int a0 = threadIdx.x, a1 = threadIdx.x + 256;
    const float c0 = g_Q[(size_t)n * DIM + a0] * 0.04419417382415922f;
    const float c1 = g_Q[(size_t)n * DIM + a1] * 0.04419417382415922f;

    float n0 = s[NMOM - 1], d0 = s[NCOEF - 1];
    float n1 = n0,          d1 = d0;
#pragma unroll
    for (int j = NMOM - 2; j >= 0; j--) {
        const float cu = s[j], cd = s[NMOM + j];
        n0 = fmaf(n0, c0, cu);  d0 = fmaf(d0, c0, cd);
        n1 = fmaf(n1, c1, cu);  d1 = fmaf(d1, c1, cd);
    }
    const float o0 = n0 / d0, o1 = n1 / d1;

    const __nv_bfloat16 h0 = __float2bfloat16(o0);
    const __nv_bfloat16 l0 = __float2bfloat16(o0 - __bfloat162float(h0));
    const __nv_bfloat16 h1 = __float2bfloat16(o1);
    const __nv_bfloat16 l1 = __float2bfloat16(o1 - __bfloat162float(h1));
    __nv_bfloat16* row = g_Op + (size_t)n * LDP;
    row[a0] = h0;  row[a0 + 512] = l0;
    row[a1] = h1;  row[a1 + 512] = l1;
}

// ---------------------------------------------------------------------------
extern "C" void kernel_launch(void* const* d_in, const int* in_sizes, int n_in,
                              void* d_out, int out_size)
{
    const float* h  = (const float*)d_in[0];
    const float* wq = (const float*)d_in[1];
    const float* wk = (const float*)d_in[2];
    const float* wv = (const float*)d_in[3];
    const float* wo = (const float*)d_in[4];
    float* out = (float*)d_out;

    static int attr_done = 0;
    if (!attr_done) {
        cudaFuncSetAttribute(qkv_gemm, cudaFuncAttributeMaxDynamicSharedMemorySize, 65536);
        cudaFuncSetAttribute(out_gemm, cudaFuncAttributeMaxDynamicSharedMemorySize, 49152);
        attr_done = 1;
    }

    split_kernel<<<(NTOK * DIM + 4 * DIM * DIM) / 256, 256>>>(h, wq, wk, wv, wo);
    qkv_gemm<<<320, 256, 65536>>>();
    moments_kernel<<<256, 256>>>();
    apply_kernel<<<NTOK, 256>>>();
    out_gemm<<<dim3(8, 16), 256, 49152>>>(out);
}

// round 7
// speedup vs baseline: 4.3011x; 1.2910x over previous
#include <cuda_runtime.h>
#include <cuda_fp16.h>
#include <cstdint>

#define NTOK 2048
#define DIM  512
#define LDP  1024              // packed [hi|lo] leading dim for h and O
#define NMOM 15
#define NCOEF (2*NMOM)

// ---------------- scratch (device globals: allocation-free) ----------------
__device__ __half g_hp [NTOK*LDP];     // h: [Ah | Al] fp16
__device__ __half g_Op [NTOK*LDP];     // O: [Oh | Ol] fp16
__device__ __half g_wqh[DIM*DIM];      // weights: hi fp16 only
__device__ __half g_wkh[DIM*DIM];
__device__ __half g_wvh[DIM*DIM];
__device__ __half g_woh[DIM*DIM];
__device__ float g_Q[NTOK*DIM], g_K[NTOK*DIM];
__device__ float g_Vp[2*NTOK*DIM];     // V partial sums (2 A-segments)
__device__ float g_C[NTOK*NCOEF];

// ---------------- PTX helpers ----------------
__device__ __forceinline__ uint32_t smem_u32(const void* p) {
    uint32_t a;
    asm("{ .reg .u64 t; cvta.to.shared.u64 t, %1; cvt.u32.u64 %0, t; }" : "=r"(a) : "l"(p));
    return a;
}
__device__ __forceinline__ void cpa16(uint32_t sdst, const void* gsrc) {
    asm volatile("cp.async.cg.shared.global [%0], [%1], 16;\n" :: "r"(sdst), "l"(gsrc));
}
#define CP_COMMIT() asm volatile("cp.async.commit_group;\n" ::: "memory")
#define CP_WAIT(n)  asm volatile("cp.async.wait_group %0;\n" :: "n"(n) : "memory")

__device__ __forceinline__ void ldsm4(uint32_t* r, uint32_t addr) {
    asm volatile("ldmatrix.sync.aligned.m8n8.x4.shared.b16 {%0,%1,%2,%3}, [%4];"
        : "=r"(r[0]), "=r"(r[1]), "=r"(r[2]), "=r"(r[3]) : "r"(addr));
}
__device__ __forceinline__ void mma_f16(float* c, const uint32_t* a,
                                        uint32_t b0, uint32_t b1) {
    asm volatile(
        "mma.sync.aligned.m16n8k16.row.col.f32.f16.f16.f32 "
        "{%0,%1,%2,%3}, {%4,%5,%6,%7}, {%8,%9}, {%0,%1,%2,%3};"
        : "+f"(c[0]), "+f"(c[1]), "+f"(c[2]), "+f"(c[3])
        : "r"(a[0]), "r"(a[1]), "r"(a[2]), "r"(a[3]), "r"(b0), "r"(b1));
}

// ---------------------------------------------------------------------------
// fp16 GEMM tile: C[m,n] = sum_k A[m,k0a+k] * B[n,kb(k)].  BM=128, BN 64|128,
// BK=64, 256 threads, 2(m) x 4(n) warps, 2-stage cp.async, 1 sync per k-iter.
// WRAPB: B k-index wraps mod 512 (A walks [hi|lo], B reuses hi).
// ---------------------------------------------------------------------------
template<int BN>
__device__ __forceinline__ void gemm_fill(uint32_t base,
    const __half* A, int lda, int ka,
    const __half* B, int ldb, int kb, int tid)
{
#pragma unroll
    for (int i = 0; i < 4; i++) {                       // A: 128 rows x 8 units
        const int idx = i * 256 + tid;
        const int r = idx >> 3, u = idx & 7;
        cpa16(base + r * 128 + ((u ^ (r & 7)) << 4),
              A + (size_t)r * lda + ka + u * 8);
    }
#pragma unroll
    for (int i = 0; i < BN / 32; i++) {                 // B: BN rows x 8 units
        const int idx = i * 256 + tid;
        const int r = idx >> 3, u = idx & 7;
        cpa16(base + 16384 + r * 128 + ((u ^ (r & 7)) << 4),
              B + (size_t)r * ldb + kb + u * 8);
    }
}

template<int BN, bool WRAPB>
__device__ void gemm_tile(const __half* __restrict__ A, int lda, int k0a,
                          const __half* __restrict__ B, int ldb,
                          float* __restrict__ C,
                          int mBase, int nBase, int kIters)
{
    constexpr int BT  = BN / 64;
    constexpr int NTT = BN / 32;
    constexpr int STG = 16384 + BN * 128;

    extern __shared__ __align__(1024) char smem[];
    const uint32_t sb = smem_u32(smem);
    const int tid = threadIdx.x, lane = tid & 31, wid = tid >> 5;
    const int wm = wid >> 2, wn = wid & 3;

    const __half* Ab = A + (size_t)mBase * lda;
    const __half* Bb = B + (size_t)nBase * ldb;

    float acc[4][NTT][4];
#pragma unroll
    for (int i = 0; i < 4; i++)
#pragma unroll
        for (int j = 0; j < NTT; j++)
#pragma unroll
            for (int q = 0; q < 4; q++) acc[i][j][q] = 0.f;

    auto ka_of = [&](int it) { return k0a + it * 64; };
    auto kb_of = [&](int it) { return WRAPB ? ((it * 64) & 511) : it * 64; };

    gemm_fill<BN>(sb, Ab, lda, ka_of(0), Bb, ldb, kb_of(0), tid);
    CP_COMMIT();

    const int lrow = lane & 15, lhi = lane >> 4;

    for (int it = 0; it < kIters; ++it) {
        CP_WAIT(0);
        __syncthreads();
        if (it + 1 < kIters) {
            gemm_fill<BN>(sb + ((it + 1) & 1) * STG, Ab, lda, ka_of(it + 1),
                          Bb, ldb, kb_of(it + 1), tid);
            CP_COMMIT();
        }
        const uint32_t base = sb + (it & 1) * STG;
#pragma unroll
        for (int ks = 0; ks < 4; ks++) {
            const int u = ks * 2 + lhi;
            uint32_t a[4][4], b[BT][4];
#pragma unroll
            for (int mt = 0; mt < 4; mt++) {
                const int r = wm * 64 + mt * 16 + lrow;
                ldsm4(a[mt], base + r * 128 + ((u ^ (r & 7)) << 4));
            }
#pragma unroll
            for (int bt = 0; bt < BT; bt++) {
                const int r = wn * (BN / 4) + bt * 16 + lrow;
                ldsm4(b[bt], base + 16384 + r * 128 + ((u ^ (r & 7)) << 4));
            }
#pragma unroll
            for (int mt = 0; mt < 4; mt++)
#pragma unroll
                for (int nt = 0; nt < NTT; nt++) {
                    const uint32_t b0 = (nt & 1) ? b[nt >> 1][1] : b[nt >> 1][0];
                    const uint32_t b1 = (nt & 1) ? b[nt >> 1][3] : b[nt >> 1][2];
                    mma_f16(acc[mt][nt], a[mt], b0, b1);
                }
        }
    }

    const int crow = mBase + wm * 64 + (lane >> 2);
    const int ccol = nBase + wn * (BN / 4) + (lane & 3) * 2;
#pragma unroll
    for (int mt = 0; mt < 4; mt++)
#pragma unroll
        for (int nt = 0; nt < NTT; nt++) {
            float* p0 = C + (size_t)(crow + mt * 16) * DIM + ccol + nt * 8;
            float* p1 = p0 + 8 * DIM;
            *(float2*)p0 = make_float2(acc[mt][nt][0], acc[mt][nt][1]);
            *(float2*)p1 = make_float2(acc[mt][nt][2], acc[mt][nt][3]);
        }
}

// Uniform QKV: 256 CTAs x 8 k-iters (single wave at occ 2).
//   [0,64): Q (1-term)   [64,128): K (1-term)
//   [128,256): V, A-segment s = (j-128)>>6 -> partial buffer g_Vp[s]
__global__ void __launch_bounds__(256, 2)
qkv_gemm()
{
    const int j = blockIdx.x;
    if (j < 128) {
        const int q = (j < 64);
        const int t = j & 63;
        gemm_tile<128, false>(g_hp, LDP, 0,
                              q ? g_wqh : g_wkh, DIM,
                              q ? g_Q : g_K,
                              (t >> 2) * 128, (t & 3) * 128, 8);
    } else {
        const int t = j - 128;
        const int s = t >> 6, tt = t & 63;
        gemm_tile<128, false>(g_hp, LDP, s * 512,
                              g_wvh, DIM,
                              g_Vp + (size_t)s * NTOK * DIM,
                              (tt >> 2) * 128, (tt & 3) * 128, 8);
    }
}

// out = [Oh|Ol] @ Woh^T : A walks K=1024, B wraps mod 512. 128 CTAs x 16 iters.
__global__ void __launch_bounds__(256, 2)
out_gemm(float* __restrict__ out)
{
    gemm_tile<64, true>(g_Op, LDP, 0, g_woh, DIM, out,
                        blockIdx.y * 128, blockIdx.x * 64, 16);
}

// ---------------- fp32 -> fp16 split (h: hi/lo; weights: hi only) ----------
__global__ void __launch_bounds__(256)
split_kernel(const float* __restrict__ h,  const float* __restrict__ wq,
             const float* __restrict__ wk, const float* __restrict__ wv,
             const float* __restrict__ wo)
{
    const int i = blockIdx.x * 256 + threadIdx.x;
    if (i < NTOK * DIM) {
        const int r = i >> 9, k = i & 511;
        const float x = h[i];
        const __half hi = __float2half_rn(x);
        g_hp[(size_t)r * LDP + k]       = hi;
        g_hp[(size_t)r * LDP + k + 512] = __float2half_rn(x - __half2float(hi));
        return;
    }
    const int j = i - NTOK * DIM;
    const int w = j >> 18;
    const int off = j & ((1 << 18) - 1);
    const float* src = (w == 0) ? wq : (w == 1) ? wk : (w == 2) ? wv : wo;
    __half* dst      = (w == 0) ? g_wqh : (w == 1) ? g_wkh : (w == 2) ? g_wvh : g_woh;
    dst[off] = __float2half_rn(src[off]);
}

// ---------------- moments: deg-14 Taylor coefficients per token -------------
// 2 interleaved power chains per lane to halve the serial multiply latency.
__global__ void __launch_bounds__(256)
moments_kernel()
{
    const int warp = (blockIdx.x * blockDim.x + threadIdx.x) >> 5;
    const int lane = threadIdx.x & 31;
    if (warp >= NTOK) return;
    const float* kp  = g_K  + (size_t)warp * DIM;
    const float* vp0 = g_Vp + (size_t)warp * DIM;
    const float* vp1 = vp0 + (size_t)NTOK * DIM;
    float um[NMOM], mm[NMOM];
#pragma unroll
    for (int j = 0; j < NMOM; j++) { um[j] = 0.f; mm[j] = 0.f; }
    for (int b = lane; b < DIM; b += 64) {
        const int b2 = b + 32;
        const float k0 = kp[b],             k1 = kp[b2];
        const float v0 = vp0[b]  + vp1[b];
        const float v1 = vp0[b2] + vp1[b2];
        float p0 = 1.f, p1 = 1.f;
#pragma unroll
        for (int j = 0; j < NMOM; j++) {
            mm[j] += p0;              mm[j] += p1;
            um[j] = fmaf(p0, v0, um[j]);
            um[j] = fmaf(p1, v1, um[j]);
            p0 *= k0;                 p1 *= k1;
        }
    }
#pragma unroll
    for (int j = 0; j < NMOM; j++)
#pragma unroll
        for (int off = 16; off > 0; off >>= 1) {
            mm[j] += __shfl_xor_sync(0xFFFFFFFFu, mm[j], off);
            um[j] += __shfl_xor_sync(0xFFFFFFFFu, um[j], off);
        }
    if (lane == 0) {
        float fact = 1.f;
        float* dst = g_C + (size_t)warp * NCOEF;
#pragma unroll
        for (int j = 0; j < NMOM; j++) {
            if (j > 0) fact *= (float)j;
            const float inv = 1.0f / fact;
            dst[j]        = um[j] * inv;
            dst[NMOM + j] = mm[j] * inv;
        }
    }
}

// ---------------- apply: o = num(c)/den(c); 4 outputs/thread ----------------
__global__ void __launch_bounds__(128)
apply_kernel()
{
    const int n = blockIdx.x;
    __shared__ float s[NCOEF];
    if (threadIdx.x < NCOEF) s[threadIdx.x] = g_C[(size_t)n * NCOEF + threadIdx.x];
    __syncthreads();

    const float* qrow = g_Q + (size_t)n * DIM;
    float c[4], nu[4], de[4];
#pragma unroll
    for (int t = 0; t < 4; t++) {
        c[t]  = qrow[threadIdx.x + t * 128] * 0.04419417382415922f;
        nu[t] = s[NMOM - 1];
        de[t] = s[NCOEF - 1];
    }
#pragma unroll
    for (int j = NMOM - 2; j >= 0; j--) {
        const float cu = s[j], cd = s[NMOM + j];
#pragma unroll
        for (int t = 0; t < 4; t++) {
            nu[t] = fmaf(nu[t], c[t], cu);
            de[t] = fmaf(de[t], c[t], cd);
        }
    }
    __half* row = g_Op + (size_t)n * LDP;
#pragma unroll
    for (int t = 0; t < 4; t++) {
        const float o = nu[t] / de[t];
        const __half hi = __float2half_rn(o);
        const int a = threadIdx.x + t * 128;
        row[a]       = hi;
        row[a + 512] = __float2half_rn(o - __half2float(hi));
    }
}

// ---------------------------------------------------------------------------
extern "C" void kernel_launch(void* const* d_in, const int* in_sizes, int n_in,
                              void* d_out, int out_size)
{
    const float* h  = (const float*)d_in[0];
    const float* wq = (const float*)d_in[1];
    const float* wk = (const float*)d_in[2];
    const float* wv = (const float*)d_in[3];
    const float* wo = (const float*)d_in[4];
    float* out = (float*)d_out;

    static int attr_done = 0;
    if (!attr_done) {
        cudaFuncSetAttribute(qkv_gemm, cudaFuncAttributeMaxDynamicSharedMemorySize, 65536);
        cudaFuncSetAttribute(out_gemm, cudaFuncAttributeMaxDynamicSharedMemorySize, 49152);
        attr_done = 1;
    }

    split_kernel<<<(NTOK * DIM + 4 * DIM * DIM) / 256, 256>>>(h, wq, wk, wv, wo);
    qkv_gemm<<<256, 256, 65536>>>();
    moments_kernel<<<256, 256>>>();
    apply_kernel<<<NTOK, 128>>>();
    out_gemm<<<dim3(8, 16), 256, 49152>>>(out);
}

// round 8
// speedup vs baseline: 4.7513x; 1.1047x over previous
#include <cuda_runtime.h>
#include <cuda_fp16.h>
#include <cstdint>

#define NTOK 2048
#define DIM  512
#define NMOM 13
#define NCOEF (2*NMOM)

// ---------------- scratch (device globals: allocation-free) ----------------
__device__ __half g_hh [NTOK*DIM];     // h   fp16 (1-term everywhere)
__device__ __half g_Oh [NTOK*DIM];     // O   fp16
__device__ __half g_wqh[DIM*DIM];
__device__ __half g_wkh[DIM*DIM];
__device__ __half g_wvh[DIM*DIM];
__device__ __half g_woh[DIM*DIM];
__device__ float g_Q[NTOK*DIM], g_K[NTOK*DIM], g_V[NTOK*DIM];

// ---------------- PTX helpers ----------------
__device__ __forceinline__ uint32_t smem_u32(const void* p) {
    uint32_t a;
    asm("{ .reg .u64 t; cvta.to.shared.u64 t, %1; cvt.u32.u64 %0, t; }" : "=r"(a) : "l"(p));
    return a;
}
__device__ __forceinline__ void cpa16(uint32_t sdst, const void* gsrc) {
    asm volatile("cp.async.cg.shared.global [%0], [%1], 16;\n" :: "r"(sdst), "l"(gsrc));
}
#define CP_COMMIT() asm volatile("cp.async.commit_group;\n" ::: "memory")
#define CP_WAIT(n)  asm volatile("cp.async.wait_group %0;\n" :: "n"(n) : "memory")

__device__ __forceinline__ void ldsm4(uint32_t* r, uint32_t addr) {
    asm volatile("ldmatrix.sync.aligned.m8n8.x4.shared.b16 {%0,%1,%2,%3}, [%4];"
        : "=r"(r[0]), "=r"(r[1]), "=r"(r[2]), "=r"(r[3]) : "r"(addr));
}
__device__ __forceinline__ void mma_f16(float* c, const uint32_t* a,
                                        uint32_t b0, uint32_t b1) {
    asm volatile(
        "mma.sync.aligned.m16n8k16.row.col.f32.f16.f16.f32 "
        "{%0,%1,%2,%3}, {%4,%5,%6,%7}, {%8,%9}, {%0,%1,%2,%3};"
        : "+f"(c[0]), "+f"(c[1]), "+f"(c[2]), "+f"(c[3])
        : "r"(a[0]), "r"(a[1]), "r"(a[2]), "r"(a[3]), "r"(b0), "r"(b1));
}

// ---------------------------------------------------------------------------
// fp16 GEMM tile: C[m,n] = sum_k A[m,k]*B[n,k], K = kIters*64.  BM=128,
// BN 64|128, BK=64, 256 threads, 2(m)x4(n) warps, 2-stage cp.async pipeline.
// ---------------------------------------------------------------------------
template<int BN>
__device__ __forceinline__ void gemm_fill(uint32_t base,
    const __half* A, const __half* B, int k0, int tid)
{
#pragma unroll
    for (int i = 0; i < 4; i++) {                       // A: 128 rows x 8 units
        const int idx = i * 256 + tid;
        const int r = idx >> 3, u = idx & 7;
        cpa16(base + r * 128 + ((u ^ (r & 7)) << 4),
              A + (size_t)r * DIM + k0 + u * 8);
    }
#pragma unroll
    for (int i = 0; i < BN / 32; i++) {                 // B: BN rows x 8 units
        const int idx = i * 256 + tid;
        const int r = idx >> 3, u = idx & 7;
        cpa16(base + 16384 + r * 128 + ((u ^ (r & 7)) << 4),
              B + (size_t)r * DIM + k0 + u * 8);
    }
}

template<int BN>
__device__ void gemm_tile(const __half* __restrict__ A,
                          const __half* __restrict__ B,
                          float* __restrict__ C,
                          int mBase, int nBase, int kIters)
{
    constexpr int BT  = BN / 64;
    constexpr int NTT = BN / 32;
    constexpr int STG = 16384 + BN * 128;

    extern __shared__ __align__(1024) char smem[];
    const uint32_t sb = smem_u32(smem);
    const int tid = threadIdx.x, lane = tid & 31, wid = tid >> 5;
    const int wm = wid >> 2, wn = wid & 3;

    const __half* Ab = A + (size_t)mBase * DIM;
    const __half* Bb = B + (size_t)nBase * DIM;

    float acc[4][NTT][4];
#pragma unroll
    for (int i = 0; i < 4; i++)
#pragma unroll
        for (int j = 0; j < NTT; j++)
#pragma unroll
            for (int q = 0; q < 4; q++) acc[i][j][q] = 0.f;

    gemm_fill<BN>(sb, Ab, Bb, 0, tid);
    CP_COMMIT();

    const int lrow = lane & 15, lhi = lane >> 4;

    for (int it = 0; it < kIters; ++it) {
        CP_WAIT(0);
        __syncthreads();
        if (it + 1 < kIters) {
            gemm_fill<BN>(sb + ((it + 1) & 1) * STG, Ab, Bb, (it + 1) * 64, tid);
            CP_COMMIT();
        }
        const uint32_t base = sb + (it & 1) * STG;
#pragma unroll
        for (int ks = 0; ks < 4; ks++) {
            const int u = ks * 2 + lhi;
            uint32_t a[4][4], b[BT][4];
#pragma unroll
            for (int mt = 0; mt < 4; mt++) {
                const int r = wm * 64 + mt * 16 + lrow;
                ldsm4(a[mt], base + r * 128 + ((u ^ (r & 7)) << 4));
            }
#pragma unroll
            for (int bt = 0; bt < BT; bt++) {
                const int r = wn * (BN / 4) + bt * 16 + lrow;
                ldsm4(b[bt], base + 16384 + r * 128 + ((u ^ (r & 7)) << 4));
            }
#pragma unroll
            for (int mt = 0; mt < 4; mt++)
#pragma unroll
                for (int nt = 0; nt < NTT; nt++) {
                    const uint32_t b0 = (nt & 1) ? b[nt >> 1][1] : b[nt >> 1][0];
                    const uint32_t b1 = (nt & 1) ? b[nt >> 1][3] : b[nt >> 1][2];
                    mma_f16(acc[mt][nt], a[mt], b0, b1);
                }
        }
    }

    const int crow = mBase + wm * 64 + (lane >> 2);
    const int ccol = nBase + wn * (BN / 4) + (lane & 3) * 2;
#pragma unroll
    for (int mt = 0; mt < 4; mt++)
#pragma unroll
        for (int nt = 0; nt < NTT; nt++) {
            float* p0 = C + (size_t)(crow + mt * 16) * DIM + ccol + nt * 8;
            float* p1 = p0 + 8 * DIM;
            *(float2*)p0 = make_float2(acc[mt][nt][0], acc[mt][nt][1]);
            *(float2*)p1 = make_float2(acc[mt][nt][2], acc[mt][nt][3]);
        }
}

// Uniform QKV: 192 CTAs x 8 k-iters (single wave at occ 2).
__global__ void __launch_bounds__(256, 2)
qkv_gemm()
{
    const int j = blockIdx.x;
    const int which = j >> 6, t = j & 63;
    const __half* B = (which == 0) ? g_wqh : (which == 1) ? g_wkh : g_wvh;
    float*       C  = (which == 0) ? g_Q   : (which == 1) ? g_K   : g_V;
    gemm_tile<128>(g_hh, B, C, (t >> 2) * 128, (t & 3) * 128, 8);
}

__global__ void __launch_bounds__(256, 2)
out_gemm(float* __restrict__ out)
{
    gemm_tile<64>(g_Oh, g_woh, out, blockIdx.y * 128, blockIdx.x * 64, 8);
}

// ---------------- fp32 -> fp16 convert (vectorized) -------------------------
__global__ void __launch_bounds__(256)
split_kernel(const float* __restrict__ h,  const float* __restrict__ wq,
             const float* __restrict__ wk, const float* __restrict__ wv,
             const float* __restrict__ wo)
{
    const int i = blockIdx.x * 256 + threadIdx.x;   // vec4 index
    const float4* src; __half* dst; int off;
    if (i < 262144) { src = (const float4*)h; dst = g_hh; off = i; }
    else {
        const int j = i - 262144;
        const int w = j >> 16;
        off = j & 65535;
        src = (const float4*)((w == 0) ? wq : (w == 1) ? wk : (w == 2) ? wv : wo);
        dst = (w == 0) ? g_wqh : (w == 1) ? g_wkh : (w == 2) ? g_wvh : g_woh;
    }
    const float4 x = src[off];
    __half2* d = (__half2*)(dst + (size_t)off * 4);
    d[0] = __floats2half2_rn(x.x, x.y);
    d[1] = __floats2half2_rn(x.z, x.w);
}

// ---------------------------------------------------------------------------
// Fused moments + apply.  Block per token, 256 threads (8 warps).
// Phase 1: warp w accumulates k-powers over b in [w*64, w*64+64) (2 per lane),
//          warp shfl-reduce, block combine in smem, scale by 1/j!.
// Phase 2: Horner eval of num/den at c = q/sqrt(512); 2 outputs per thread.
// ---------------------------------------------------------------------------
__device__ __constant__ float c_invfact[NMOM] = {
    1.0f, 1.0f, 0.5f, 1.6666667e-1f, 4.1666668e-2f, 8.3333338e-3f,
    1.3888889e-3f, 1.9841270e-4f, 2.4801588e-5f, 2.7557319e-6f,
    2.7557319e-7f, 2.5052108e-8f, 2.0876757e-9f };

__global__ void __launch_bounds__(256)
ma_kernel()
{
    const int n    = blockIdx.x;
    const int tid  = threadIdx.x;
    const int lane = tid & 31, w = tid >> 5;

    const float* kp = g_K + (size_t)n * DIM;
    const float* vp = g_V + (size_t)n * DIM;

    const int b0 = w * 64 + lane, b1 = b0 + 32;
    const float k0 = kp[b0], k1 = kp[b1];
    const float v0 = vp[b0], v1 = vp[b1];

    float um[NMOM], mm[NMOM];
    float p0 = 1.f, p1 = 1.f;
#pragma unroll
    for (int j = 0; j < NMOM; j++) {
        mm[j] = p0 + p1;
        um[j] = fmaf(p0, v0, p1 * v1);
        p0 *= k0; p1 *= k1;
    }
#pragma unroll
    for (int j = 0; j < NMOM; j++)
#pragma unroll
        for (int off = 16; off > 0; off >>= 1) {
            mm[j] += __shfl_xor_sync(0xFFFFFFFFu, mm[j], off);
            um[j] += __shfl_xor_sync(0xFFFFFFFFu, um[j], off);
        }

    __shared__ float sp[8][NCOEF];
    __shared__ float sc[NCOEF];
    if (lane == 0) {
#pragma unroll
        for (int j = 0; j < NMOM; j++) {
            sp[w][j]        = um[j];
            sp[w][NMOM + j] = mm[j];
        }
    }
    __syncthreads();
    if (tid < NCOEF) {
        float s = 0.f;
#pragma unroll
        for (int ww = 0; ww < 8; ww++) s += sp[ww][tid];
        sc[tid] = s * c_invfact[(tid < NMOM) ? tid : tid - NMOM];
    }
    __syncthreads();

    const float* qrow = g_Q + (size_t)n * DIM;
    float c[2], nu[2], de[2];
#pragma unroll
    for (int t = 0; t < 2; t++) {
        c[t]  = qrow[tid + t * 256] * 0.04419417382415922f;
        nu[t] = sc[NMOM - 1];
        de[t] = sc[NCOEF - 1];
    }
#pragma unroll
    for (int j = NMOM - 2; j >= 0; j--) {
        const float cu = sc[j], cd = sc[NMOM + j];
#pragma unroll
        for (int t = 0; t < 2; t++) {
            nu[t] = fmaf(nu[t], c[t], cu);
            de[t] = fmaf(de[t], c[t], cd);
        }
    }
    __half* row = g_Oh + (size_t)n * DIM;
#pragma unroll
    for (int t = 0; t < 2; t++)
        row[tid + t * 256] = __float2half_rn(nu[t] / de[t]);
}

// ---------------------------------------------------------------------------
extern "C" void kernel_launch(void* const* d_in, const int* in_sizes, int n_in,
                              void* d_out, int out_size)
{
    const float* h  = (const float*)d_in[0];
    const float* wq = (const float*)d_in[1];
    const float* wk = (const float*)d_in[2];
    const float* wv = (const float*)d_in[3];
    const float* wo = (const float*)d_in[4];
    float* out = (float*)d_out;

    static int attr_done = 0;
    if (!attr_done) {
        cudaFuncSetAttribute(qkv_gemm, cudaFuncAttributeMaxDynamicSharedMemorySize, 65536);
        cudaFuncSetAttribute(out_gemm, cudaFuncAttributeMaxDynamicSharedMemorySize, 49152);
        attr_done = 1;
    }

    split_kernel<<<2048, 256>>>(h, wq, wk, wv, wo);
    qkv_gemm<<<192, 256, 65536>>>();
    ma_kernel<<<NTOK, 256>>>();
    out_gemm<<<dim3(8, 16), 256, 49152>>>(out);
}

// round 9
// speedup vs baseline: 5.1655x; 1.0872x over previous
#include <cuda_runtime.h>
#include <cuda_fp16.h>
#include <cstdint>

#define NTOK 2048
#define DIM  512
#define NMOM 13
#define NCOEF (2*NMOM)

// ---------------- scratch (device globals: allocation-free) ----------------
__device__ __half g_hh [NTOK*DIM];     // h   fp16 (1-term everywhere)
__device__ __half g_Oh [NTOK*DIM];     // O   fp16
__device__ __half g_wqh[DIM*DIM];
__device__ __half g_wkh[DIM*DIM];
__device__ __half g_wvh[DIM*DIM];
__device__ __half g_woh[DIM*DIM];
__device__ float g_Q[NTOK*DIM], g_K[NTOK*DIM], g_V[NTOK*DIM];

// ---------------- PTX helpers ----------------
__device__ __forceinline__ uint32_t smem_u32(const void* p) {
    uint32_t a;
    asm("{ .reg .u64 t; cvta.to.shared.u64 t, %1; cvt.u32.u64 %0, t; }" : "=r"(a) : "l"(p));
    return a;
}
__device__ __forceinline__ void cpa16(uint32_t sdst, const void* gsrc) {
    asm volatile("cp.async.cg.shared.global [%0], [%1], 16;\n" :: "r"(sdst), "l"(gsrc));
}
#define CP_COMMIT() asm volatile("cp.async.commit_group;\n" ::: "memory")
#define CP_WAIT(n)  asm volatile("cp.async.wait_group %0;\n" :: "n"(n) : "memory")

__device__ __forceinline__ void ldsm4(uint32_t* r, uint32_t addr) {
    asm volatile("ldmatrix.sync.aligned.m8n8.x4.shared.b16 {%0,%1,%2,%3}, [%4];"
        : "=r"(r[0]), "=r"(r[1]), "=r"(r[2]), "=r"(r[3]) : "r"(addr));
}
__device__ __forceinline__ void mma_f16(float* c, const uint32_t* a,
                                        uint32_t b0, uint32_t b1) {
    asm volatile(
        "mma.sync.aligned.m16n8k16.row.col.f32.f16.f16.f32 "
        "{%0,%1,%2,%3}, {%4,%5,%6,%7}, {%8,%9}, {%0,%1,%2,%3};"
        : "+f"(c[0]), "+f"(c[1]), "+f"(c[2]), "+f"(c[3])
        : "r"(a[0]), "r"(a[1]), "r"(a[2]), "r"(a[3]), "r"(b0), "r"(b1));
}

// ---------------------------------------------------------------------------
// fp16 GEMM tile: C[m,n] = sum_k A[m,k]*B[n,k], K = kIters*64.
// BM in {64,128}, BN in {64,128}; 256 threads, warps 2(m) x 4(n),
// 2-stage cp.async pipeline, one __syncthreads per k-iter.
// ---------------------------------------------------------------------------
template<int BM, int BN>
__device__ __forceinline__ void gemm_fill(uint32_t base,
    const __half* A, const __half* B, int k0, int tid)
{
#pragma unroll
    for (int i = 0; i < BM / 32; i++) {                 // A: BM rows x 8 units
        const int idx = i * 256 + tid;
        const int r = idx >> 3, u = idx & 7;
        cpa16(base + r * 128 + ((u ^ (r & 7)) << 4),
              A + (size_t)r * DIM + k0 + u * 8);
    }
#pragma unroll
    for (int i = 0; i < BN / 32; i++) {                 // B: BN rows x 8 units
        const int idx = i * 256 + tid;
        const int r = idx >> 3, u = idx & 7;
        cpa16(base + BM * 128 + r * 128 + ((u ^ (r & 7)) << 4),
              B + (size_t)r * DIM + k0 + u * 8);
    }
}

template<int BM, int BN>
__device__ void gemm_tile(const __half* __restrict__ A,
                          const __half* __restrict__ B,
                          float* __restrict__ C,
                          int mBase, int nBase, int kIters)
{
    constexpr int MT  = BM / 32;
    constexpr int BT  = BN / 64;
    constexpr int NTT = BN / 32;
    constexpr int STG = (BM + BN) * 128;

    extern __shared__ __align__(1024) char smem[];
    const uint32_t sb = smem_u32(smem);
    const int tid = threadIdx.x, lane = tid & 31, wid = tid >> 5;
    const int wm = wid >> 2, wn = wid & 3;

    const __half* Ab = A + (size_t)mBase * DIM;
    const __half* Bb = B + (size_t)nBase * DIM;

    float acc[MT][NTT][4];
#pragma unroll
    for (int i = 0; i < MT; i++)
#pragma unroll
        for (int j = 0; j < NTT; j++)
#pragma unroll
            for (int q = 0; q < 4; q++) acc[i][j][q] = 0.f;

    gemm_fill<BM, BN>(sb, Ab, Bb, 0, tid);
    CP_COMMIT();

    const int lrow = lane & 15, lhi = lane >> 4;

    for (int it = 0; it < kIters; ++it) {
        CP_WAIT(0);
        __syncthreads();
        if (it + 1 < kIters) {
            gemm_fill<BM, BN>(sb + ((it + 1) & 1) * STG, Ab, Bb, (it + 1) * 64, tid);
            CP_COMMIT();
        }
        const uint32_t base = sb + (it & 1) * STG;
#pragma unroll
        for (int ks = 0; ks < 4; ks++) {
            const int u = ks * 2 + lhi;
            uint32_t a[MT][4], b[BT][4];
#pragma unroll
            for (int mt = 0; mt < MT; mt++) {
                const int r = wm * (BM / 2) + mt * 16 + lrow;
                ldsm4(a[mt], base + r * 128 + ((u ^ (r & 7)) << 4));
            }
#pragma unroll
            for (int bt = 0; bt < BT; bt++) {
                const int r = wn * (BN / 4) + bt * 16 + lrow;
                ldsm4(b[bt], base + BM * 128 + r * 128 + ((u ^ (r & 7)) << 4));
            }
#pragma unroll
            for (int mt = 0; mt < MT; mt++)
#pragma unroll
                for (int nt = 0; nt < NTT; nt++) {
                    const uint32_t b0 = (nt & 1) ? b[nt >> 1][1] : b[nt >> 1][0];
                    const uint32_t b1 = (nt & 1) ? b[nt >> 1][3] : b[nt >> 1][2];
                    mma_f16(acc[mt][nt], a[mt], b0, b1);
                }
        }
    }

    const int crow = mBase + wm * (BM / 2) + (lane >> 2);
    const int ccol = nBase + wn * (BN / 4) + (lane & 3) * 2;
#pragma unroll
    for (int mt = 0; mt < MT; mt++)
#pragma unroll
        for (int nt = 0; nt < NTT; nt++) {
            float* p0 = C + (size_t)(crow + mt * 16) * DIM + ccol + nt * 8;
            float* p1 = p0 + 8 * DIM;
            *(float2*)p0 = make_float2(acc[mt][nt][0], acc[mt][nt][1]);
            *(float2*)p1 = make_float2(acc[mt][nt][2], acc[mt][nt][3]);
        }
}

// QKV: 384 CTAs (3 matrices x 32 m-tiles x 4 n-tiles), BM=64 BN=128, 8 iters.
__global__ void __launch_bounds__(256, 3)
qkv_gemm()
{
    const int j = blockIdx.x;
    const int which = j >> 7, t = j & 127;
    const __half* B = (which == 0) ? g_wqh : (which == 1) ? g_wkh : g_wvh;
    float*       C  = (which == 0) ? g_Q   : (which == 1) ? g_K   : g_V;
    gemm_tile<64, 128>(g_hh, B, C, (t >> 2) * 64, (t & 3) * 128, 8);
}

// out: 256 CTAs (32 m-tiles x 8 n-tiles), BM=64 BN=64, 8 iters.
__global__ void __launch_bounds__(256, 3)
out_gemm(float* __restrict__ out)
{
    const int t = blockIdx.x;
    gemm_tile<64, 64>(g_Oh, g_woh, out, (t >> 3) * 64, (t & 7) * 64, 8);
}

// ---------------- fp32 -> fp16 convert (vectorized) -------------------------
__global__ void __launch_bounds__(256)
split_kernel(const float* __restrict__ h,  const float* __restrict__ wq,
             const float* __restrict__ wk, const float* __restrict__ wv,
             const float* __restrict__ wo)
{
    const int i = blockIdx.x * 256 + threadIdx.x;   // vec4 index
    const float4* src; __half* dst; int off;
    if (i < 262144) { src = (const float4*)h; dst = g_hh; off = i; }
    else {
        const int j = i - 262144;
        const int w = j >> 16;
        off = j & 65535;
        src = (const float4*)((w == 0) ? wq : (w == 1) ? wk : (w == 2) ? wv : wo);
        dst = (w == 0) ? g_wqh : (w == 1) ? g_wkh : (w == 2) ? g_wvh : g_woh;
    }
    const float4 x = src[off];
    __half2* d = (__half2*)(dst + (size_t)off * 4);
    d[0] = __floats2half2_rn(x.x, x.y);
    d[1] = __floats2half2_rn(x.z, x.w);
}

// ---------------------------------------------------------------------------
// Fused moments + apply.  Block per token, 256 threads (8 warps).
// ---------------------------------------------------------------------------
__device__ __constant__ float c_invfact[NMOM] = {
    1.0f, 1.0f, 0.5f, 1.6666667e-1f, 4.1666668e-2f, 8.3333338e-3f,
    1.3888889e-3f, 1.9841270e-4f, 2.4801588e-5f, 2.7557319e-6f,
    2.7557319e-7f, 2.5052108e-8f, 2.0876757e-9f };

__global__ void __launch_bounds__(256)
ma_kernel()
{
    const int n    = blockIdx.x;
    const int tid  = threadIdx.x;
    const int lane = tid & 31, w = tid >> 5;

    const float* kp = g_K + (size_t)n * DIM;
    const float* vp = g_V + (size_t)n * DIM;

    const int b0 = w * 64 + lane, b1 = b0 + 32;
    const float k0 = kp[b0], k1 = kp[b1];
    const float v0 = vp[b0], v1 = vp[b1];

    float um[NMOM], mm[NMOM];
    float p0 = 1.f, p1 = 1.f;
#pragma unroll
    for (int j = 0; j < NMOM; j++) {
        mm[j] = p0 + p1;
        um[j] = fmaf(p0, v0, p1 * v1);
        p0 *= k0; p1 *= k1;
    }
#pragma unroll
    for (int j = 0; j < NMOM; j++)
#pragma unroll
        for (int off = 16; off > 0; off >>= 1) {
            mm[j] += __shfl_xor_sync(0xFFFFFFFFu, mm[j], off);
            um[j] += __shfl_xor_sync(0xFFFFFFFFu, um[j], off);
        }

    __shared__ float sp[8][NCOEF];
    __shared__ float sc[NCOEF];
    if (lane == 0) {
#pragma unroll
        for (int j = 0; j < NMOM; j++) {
            sp[w][j]        = um[j];
            sp[w][NMOM + j] = mm[j];
        }
    }
    __syncthreads();
    if (tid < NCOEF) {
        float s = 0.f;
#pragma unroll
        for (int ww = 0; ww < 8; ww++) s += sp[ww][tid];
        sc[tid] = s * c_invfact[(tid < NMOM) ? tid : tid - NMOM];
    }
    __syncthreads();

    const float* qrow = g_Q + (size_t)n * DIM;
    float c[2], nu[2], de[2];
#pragma unroll
    for (int t = 0; t < 2; t++) {
        c[t]  = qrow[tid + t * 256] * 0.04419417382415922f;
        nu[t] = sc[NMOM - 1];
        de[t] = sc[NCOEF - 1];
    }
#pragma unroll
    for (int j = NMOM - 2; j >= 0; j--) {
        const float cu = sc[j], cd = sc[NMOM + j];
#pragma unroll
        for (int t = 0; t < 2; t++) {
            nu[t] = fmaf(nu[t], c[t], cu);
            de[t] = fmaf(de[t], c[t], cd);
        }
    }
    __half* row = g_Oh + (size_t)n * DIM;
#pragma unroll
    for (int t = 0; t < 2; t++)
        row[tid + t * 256] = __float2half_rn(nu[t] / de[t]);
}

// ---------------------------------------------------------------------------
extern "C" void kernel_launch(void* const* d_in, const int* in_sizes, int n_in,
                              void* d_out, int out_size)
{
    const float* h  = (const float*)d_in[0];
    const float* wq = (const float*)d_in[1];
    const float* wk = (const float*)d_in[2];
    const float* wv = (const float*)d_in[3];
    const float* wo = (const float*)d_in[4];
    float* out = (float*)d_out;

    static int attr_done = 0;
    if (!attr_done) {
        cudaFuncSetAttribute(qkv_gemm, cudaFuncAttributeMaxDynamicSharedMemorySize, 49152);
        cudaFuncSetAttribute(out_gemm, cudaFuncAttributeMaxDynamicSharedMemorySize, 32768);
        attr_done = 1;
    }

    split_kernel<<<2048, 256>>>(h, wq, wk, wv, wo);
    qkv_gemm<<<384, 256, 49152>>>();
    ma_kernel<<<NTOK, 256>>>();
    out_gemm<<<256, 256, 32768>>>(out);
}

// round 10
// speedup vs baseline: 5.7554x; 1.1142x over previous
#include <cuda_runtime.h>
#include <cuda_fp16.h>
#include <cstdint>

#define NTOK 2048
#define DIM  512
#define NMOM 13
#define NCOEF (2*NMOM)

// ---------------- scratch (device globals: allocation-free) ----------------
__device__ __half g_hh [NTOK*DIM];
__device__ __half g_Oh [NTOK*DIM];
__device__ __half g_wqh[DIM*DIM];
__device__ __half g_wkh[DIM*DIM];
__device__ __half g_wvh[DIM*DIM];
__device__ __half g_woh[DIM*DIM];
__device__ float g_Q[NTOK*DIM], g_K[NTOK*DIM], g_V[NTOK*DIM];

// ---------------- PTX helpers ----------------
__device__ __forceinline__ uint32_t smem_u32(const void* p) {
    uint32_t a;
    asm("{ .reg .u64 t; cvta.to.shared.u64 t, %1; cvt.u32.u64 %0, t; }" : "=r"(a) : "l"(p));
    return a;
}
__device__ __forceinline__ void cpa16(uint32_t sdst, const void* gsrc) {
    asm volatile("cp.async.cg.shared.global [%0], [%1], 16;\n" :: "r"(sdst), "l"(gsrc));
}
#define CP_COMMIT() asm volatile("cp.async.commit_group;\n" ::: "memory")
#define CP_WAIT(n)  asm volatile("cp.async.wait_group %0;\n" :: "n"(n) : "memory")

__device__ __forceinline__ void ldsm4(uint32_t* r, uint32_t addr) {
    asm volatile("ldmatrix.sync.aligned.m8n8.x4.shared.b16 {%0,%1,%2,%3}, [%4];"
        : "=r"(r[0]), "=r"(r[1]), "=r"(r[2]), "=r"(r[3]) : "r"(addr));
}
__device__ __forceinline__ void mma_f16(float* c, const uint32_t* a,
                                        uint32_t b0, uint32_t b1) {
    asm volatile(
        "mma.sync.aligned.m16n8k16.row.col.f32.f16.f16.f32 "
        "{%0,%1,%2,%3}, {%4,%5,%6,%7}, {%8,%9}, {%0,%1,%2,%3};"
        : "+f"(c[0]), "+f"(c[1]), "+f"(c[2]), "+f"(c[3])
        : "r"(a[0]), "r"(a[1]), "r"(a[2]), "r"(a[3]), "r"(b0), "r"(b1));
}

// ---------------------------------------------------------------------------
// fp16 GEMM tile, 4-stage cp.async pipeline.  C[m,n] = sum_k A[m,k]*B[n,k].
// BM/BN in {64,128}; 256 threads, warps 2(m) x 4(n); K = kIters*64.
// ---------------------------------------------------------------------------
template<int BM, int BN>
__device__ __forceinline__ void gemm_fill(uint32_t base,
    const __half* A, const __half* B, int k0, int tid)
{
#pragma unroll
    for (int i = 0; i < BM / 32; i++) {
        const int idx = i * 256 + tid;
        const int r = idx >> 3, u = idx & 7;
        cpa16(base + r * 128 + ((u ^ (r & 7)) << 4),
              A + (size_t)r * DIM + k0 + u * 8);
    }
#pragma unroll
    for (int i = 0; i < BN / 32; i++) {
        const int idx = i * 256 + tid;
        const int r = idx >> 3, u = idx & 7;
        cpa16(base + BM * 128 + r * 128 + ((u ^ (r & 7)) << 4),
              B + (size_t)r * DIM + k0 + u * 8);
    }
}

template<int BM, int BN>
__device__ void gemm_tile(const __half* __restrict__ A,
                          const __half* __restrict__ B,
                          float* __restrict__ C,
                          int mBase, int nBase, int kIters)
{
    constexpr int MT  = BM / 32;
    constexpr int BT  = BN / 64;
    constexpr int NTT = BN / 32;
    constexpr int STG = (BM + BN) * 128;

    extern __shared__ __align__(1024) char smem[];
    const uint32_t sb = smem_u32(smem);
    const int tid = threadIdx.x, lane = tid & 31, wid = tid >> 5;
    const int wm = wid >> 2, wn = wid & 3;

    const __half* Ab = A + (size_t)mBase * DIM;
    const __half* Bb = B + (size_t)nBase * DIM;

    float acc[MT][NTT][4];
#pragma unroll
    for (int i = 0; i < MT; i++)
#pragma unroll
        for (int j = 0; j < NTT; j++)
#pragma unroll
            for (int q = 0; q < 4; q++) acc[i][j][q] = 0.f;

    // Prologue: fill stages 0..2 (3 committed groups in flight).
#pragma unroll
    for (int s = 0; s < 3; s++) {
        gemm_fill<BM, BN>(sb + s * STG, Ab, Bb, s * 64, tid);
        CP_COMMIT();
    }

    const int lrow = lane & 15, lhi = lane >> 4;

    for (int it = 0; it < kIters; ++it) {
        CP_WAIT(2);               // fill(it) complete; 2 younger groups in flight
        __syncthreads();
        // Refill stage (it+3)%4 — last consumed at iter it-1, ordered by the sync.
        if (it + 3 < kIters)
            gemm_fill<BM, BN>(sb + ((it + 3) & 3) * STG, Ab, Bb, (it + 3) * 64, tid);
        CP_COMMIT();              // (possibly empty group — keeps wait count honest)

        const uint32_t base = sb + (it & 3) * STG;
#pragma unroll
        for (int ks = 0; ks < 4; ks++) {
            const int u = ks * 2 + lhi;
            uint32_t a[MT][4], b[BT][4];
#pragma unroll
            for (int mt = 0; mt < MT; mt++) {
                const int r = wm * (BM / 2) + mt * 16 + lrow;
                ldsm4(a[mt], base + r * 128 + ((u ^ (r & 7)) << 4));
            }
#pragma unroll
            for (int bt = 0; bt < BT; bt++) {
                const int r = wn * (BN / 4) + bt * 16 + lrow;
                ldsm4(b[bt], base + BM * 128 + r * 128 + ((u ^ (r & 7)) << 4));
            }
#pragma unroll
            for (int mt = 0; mt < MT; mt++)
#pragma unroll
                for (int nt = 0; nt < NTT; nt++) {
                    const uint32_t b0 = (nt & 1) ? b[nt >> 1][1] : b[nt >> 1][0];
                    const uint32_t b1 = (nt & 1) ? b[nt >> 1][3] : b[nt >> 1][2];
                    mma_f16(acc[mt][nt], a[mt], b0, b1);
                }
        }
    }

    const int crow = mBase + wm * (BM / 2) + (lane >> 2);
    const int ccol = nBase + wn * (BN / 4) + (lane & 3) * 2;
#pragma unroll
    for (int mt = 0; mt < MT; mt++)
#pragma unroll
        for (int nt = 0; nt < NTT; nt++) {
            float* p0 = C + (size_t)(crow + mt * 16) * DIM + ccol + nt * 8;
            float* p1 = p0 + 8 * DIM;
            *(float2*)p0 = make_float2(acc[mt][nt][0], acc[mt][nt][1]);
            *(float2*)p1 = make_float2(acc[mt][nt][2], acc[mt][nt][3]);
        }
}

// QKV: 384 CTAs (3 matrices x 32 m-tiles x 4 n-tiles), BM=64 BN=128.
__global__ void __launch_bounds__(256, 2)
qkv_gemm()
{
    const int j = blockIdx.x;
    const int which = j >> 7, t = j & 127;
    const __half* B = (which == 0) ? g_wqh : (which == 1) ? g_wkh : g_wvh;
    float*       C  = (which == 0) ? g_Q   : (which == 1) ? g_K   : g_V;
    gemm_tile<64, 128>(g_hh, B, C, (t >> 2) * 64, (t & 3) * 128, 8);
}

// out: 256 CTAs (32 m-tiles x 8 n-tiles), BM=64 BN=64.
__global__ void __launch_bounds__(256, 3)
out_gemm(float* __restrict__ out)
{
    const int t = blockIdx.x;
    gemm_tile<64, 64>(g_Oh, g_woh, out, (t >> 3) * 64, (t & 7) * 64, 8);
}

// ---------------- fp32 -> fp16 convert (vectorized) -------------------------
__global__ void __launch_bounds__(256)
split_kernel(const float* __restrict__ h,  const float* __restrict__ wq,
             const float* __restrict__ wk, const float* __restrict__ wv,
             const float* __restrict__ wo)
{
    const int i = blockIdx.x * 256 + threadIdx.x;   // vec4 index
    const float4* src; __half* dst; int off;
    if (i < 262144) { src = (const float4*)h; dst = g_hh; off = i; }
    else {
        const int j = i - 262144;
        const int w = j >> 16;
        off = j & 65535;
        src = (const float4*)((w == 0) ? wq : (w == 1) ? wk : (w == 2) ? wv : wo);
        dst = (w == 0) ? g_wqh : (w == 1) ? g_wkh : (w == 2) ? g_wvh : g_woh;
    }
    const float4 x = src[off];
    __half2* d = (__half2*)(dst + (size_t)off * 4);
    d[0] = __floats2half2_rn(x.x, x.y);
    d[1] = __floats2half2_rn(x.z, x.w);
}

// ---------------------------------------------------------------------------
// Fused moments + apply.  Block per token, 256 threads (8 warps).
// Phase 1: per-thread 26 partials (2 b-values each) -> smem [26][256].
// Phase 2: warp w reduces coefs {w, w+8, w+16, w+24<26}: 8 LDS + shfl tree.
// Phase 3: Horner eval of num/den at c = q/sqrt(512); 2 outputs per thread.
// ---------------------------------------------------------------------------
__device__ __constant__ float c_invfact[NMOM] = {
    1.0f, 1.0f, 0.5f, 1.6666667e-1f, 4.1666668e-2f, 8.3333338e-3f,
    1.3888889e-3f, 1.9841270e-4f, 2.4801588e-5f, 2.7557319e-6f,
    2.7557319e-7f, 2.5052108e-8f, 2.0876757e-9f };

__global__ void __launch_bounds__(256)
ma_kernel()
{
    const int n    = blockIdx.x;
    const int tid  = threadIdx.x;
    const int lane = tid & 31, w = tid >> 5;

    __shared__ float sp[NCOEF][256];
    __shared__ float sc[NCOEF];

    const float* kp = g_K + (size_t)n * DIM;
    const float* vp = g_V + (size_t)n * DIM;

    const float k0 = kp[tid], k1 = kp[tid + 256];
    const float v0 = vp[tid], v1 = vp[tid + 256];

    {
        float p0 = 1.f, p1 = 1.f;
#pragma unroll
        for (int j = 0; j < NMOM; j++) {
            sp[NMOM + j][tid] = p0 + p1;
            sp[j][tid]        = fmaf(p0, v0, p1 * v1);
            p0 *= k0; p1 *= k1;
        }
    }
    __syncthreads();

#pragma unroll
    for (int cc = 0; cc < 4; cc++) {
        const int c = w + cc * 8;
        if (c < NCOEF) {
            float s = 0.f;
#pragma unroll
            for (int q = 0; q < 8; q++) s += sp[c][lane + q * 32];
#pragma unroll
            for (int off = 16; off > 0; off >>= 1)
                s += __shfl_xor_sync(0xFFFFFFFFu, s, off);
            if (lane == 0)
                sc[c] = s * c_invfact[(c < NMOM) ? c : c - NMOM];
        }
    }
    __syncthreads();

    const float* qrow = g_Q + (size_t)n * DIM;
    float c[2], nu[2], de[2];
#pragma unroll
    for (int t = 0; t < 2; t++) {
        c[t]  = qrow[tid + t * 256] * 0.04419417382415922f;
        nu[t] = sc[NMOM - 1];
        de[t] = sc[NCOEF - 1];
    }
#pragma unroll
    for (int j = NMOM - 2; j >= 0; j--) {
        const float cu = sc[j], cd = sc[NMOM + j];
#pragma unroll
        for (int t = 0; t < 2; t++) {
            nu[t] = fmaf(nu[t], c[t], cu);
            de[t] = fmaf(de[t], c[t], cd);
        }
    }
    __half* row = g_Oh + (size_t)n * DIM;
#pragma unroll
    for (int t = 0; t < 2; t++)
        row[tid + t * 256] = __float2half_rn(nu[t] / de[t]);
}

// ---------------------------------------------------------------------------
extern "C" void kernel_launch(void* const* d_in, const int* in_sizes, int n_in,
                              void* d_out, int out_size)
{
    const float* h  = (const float*)d_in[0];
    const float* wq = (const float*)d_in[1];
    const float* wk = (const float*)d_in[2];
    const float* wv = (const float*)d_in[3];
    const float* wo = (const float*)d_in[4];
    float* out = (float*)d_out;

    static int attr_done = 0;
    if (!attr_done) {
        cudaFuncSetAttribute(qkv_gemm, cudaFuncAttributeMaxDynamicSharedMemorySize, 98304);
        cudaFuncSetAttribute(out_gemm, cudaFuncAttributeMaxDynamicSharedMemorySize, 65536);
        attr_done = 1;
    }

    split_kernel<<<2048, 256>>>(h, wq, wk, wv, wo);
    qkv_gemm<<<384, 256, 98304>>>();
    ma_kernel<<<NTOK, 256>>>();
    out_gemm<<<256, 256, 65536>>>(out);
}

// round 11
// speedup vs baseline: 5.7971x; 1.0072x over previous
#include <cuda_runtime.h>
#include <cuda_fp16.h>
#include <cstdint>

#define NTOK 2048
#define DIM  512
#define NMOM 13
#define NCOEF (2*NMOM)

// ---------------- scratch (device globals: allocation-free) ----------------
__device__ __half g_hh [NTOK*DIM];
__device__ __half g_Oh [NTOK*DIM];
__device__ __half g_wqh[DIM*DIM];
__device__ __half g_wkh[DIM*DIM];
__device__ __half g_wvh[DIM*DIM];
__device__ __half g_woh[DIM*DIM];
__device__ float g_Q[NTOK*DIM], g_K[NTOK*DIM], g_V[NTOK*DIM];

// ---------------- PTX helpers ----------------
__device__ __forceinline__ uint32_t smem_u32(const void* p) {
    uint32_t a;
    asm("{ .reg .u64 t; cvta.to.shared.u64 t, %1; cvt.u32.u64 %0, t; }" : "=r"(a) : "l"(p));
    return a;
}
__device__ __forceinline__ void cpa16(uint32_t sdst, const void* gsrc) {
    asm volatile("cp.async.cg.shared.global [%0], [%1], 16;\n" :: "r"(sdst), "l"(gsrc));
}
#define CP_COMMIT() asm volatile("cp.async.commit_group;\n" ::: "memory")
#define CP_WAIT(n)  asm volatile("cp.async.wait_group %0;\n" :: "n"(n) : "memory")

__device__ __forceinline__ void ldsm4(uint32_t* r, uint32_t addr) {
    asm volatile("ldmatrix.sync.aligned.m8n8.x4.shared.b16 {%0,%1,%2,%3}, [%4];"
        : "=r"(r[0]), "=r"(r[1]), "=r"(r[2]), "=r"(r[3]) : "r"(addr));
}
__device__ __forceinline__ void mma_f16(float* c, const uint32_t* a,
                                        uint32_t b0, uint32_t b1) {
    asm volatile(
        "mma.sync.aligned.m16n8k16.row.col.f32.f16.f16.f32 "
        "{%0,%1,%2,%3}, {%4,%5,%6,%7}, {%8,%9}, {%0,%1,%2,%3};"
        : "+f"(c[0]), "+f"(c[1]), "+f"(c[2]), "+f"(c[3])
        : "r"(a[0]), "r"(a[1]), "r"(a[2]), "r"(a[3]), "r"(b0), "r"(b1));
}

// ---------------------------------------------------------------------------
// fp16 GEMM tile, 4-stage cp.async pipeline + register double-buffered ldsm.
// C[m,n] = sum_k A[m,k]*B[n,k].  BM/BN in {64,128}; 256 threads,
// warps 2(m) x 4(n); K = kIters*64.
// ---------------------------------------------------------------------------
template<int BM, int BN>
__device__ __forceinline__ void gemm_fill(uint32_t base,
    const __half* A, const __half* B, int k0, int tid)
{
#pragma unroll
    for (int i = 0; i < BM / 32; i++) {
        const int idx = i * 256 + tid;
        const int r = idx >> 3, u = idx & 7;
        cpa16(base + r * 128 + ((u ^ (r & 7)) << 4),
              A + (size_t)r * DIM + k0 + u * 8);
    }
#pragma unroll
    for (int i = 0; i < BN / 32; i++) {
        const int idx = i * 256 + tid;
        const int r = idx >> 3, u = idx & 7;
        cpa16(base + BM * 128 + r * 128 + ((u ^ (r & 7)) << 4),
              B + (size_t)r * DIM + k0 + u * 8);
    }
}

template<int BM, int BN>
__device__ void gemm_tile(const __half* __restrict__ A,
                          const __half* __restrict__ B,
                          float* __restrict__ C,
                          int mBase, int nBase, int kIters)
{
    constexpr int MT  = BM / 32;
    constexpr int BT  = BN / 64;
    constexpr int NTT = BN / 32;
    constexpr int STG = (BM + BN) * 128;

    extern __shared__ __align__(1024) char smem[];
    const uint32_t sb = smem_u32(smem);
    const int tid = threadIdx.x, lane = tid & 31, wid = tid >> 5;
    const int wm = wid >> 2, wn = wid & 3;

    const __half* Ab = A + (size_t)mBase * DIM;
    const __half* Bb = B + (size_t)nBase * DIM;

    float acc[MT][NTT][4];
#pragma unroll
    for (int i = 0; i < MT; i++)
#pragma unroll
        for (int j = 0; j < NTT; j++)
#pragma unroll
            for (int q = 0; q < 4; q++) acc[i][j][q] = 0.f;

    // Prologue: fill stages 0..2 (3 committed groups in flight).
#pragma unroll
    for (int s = 0; s < 3; s++) {
        gemm_fill<BM, BN>(sb + s * STG, Ab, Bb, s * 64, tid);
        CP_COMMIT();
    }

    const int lrow = lane & 15, lhi = lane >> 4;

    for (int it = 0; it < kIters; ++it) {
        CP_WAIT(2);               // fill(it) complete; 2 younger groups in flight
        __syncthreads();
        if (it + 3 < kIters)      // refill stage (it+3)%4 (consumed at it-1)
            gemm_fill<BM, BN>(sb + ((it + 3) & 3) * STG, Ab, Bb, (it + 3) * 64, tid);
        CP_COMMIT();              // possibly-empty group keeps wait count honest

        const uint32_t base = sb + (it & 3) * STG;

        uint32_t a[2][MT][4], b[2][BT][4];
        auto ldfrag = [&](int buf, int ks) {
            const int u = ks * 2 + lhi;
#pragma unroll
            for (int mt = 0; mt < MT; mt++) {
                const int r = wm * (BM / 2) + mt * 16 + lrow;
                ldsm4(a[buf][mt], base + r * 128 + ((u ^ (r & 7)) << 4));
            }
#pragma unroll
            for (int bt = 0; bt < BT; bt++) {
                const int r = wn * (BN / 4) + bt * 16 + lrow;
                ldsm4(b[buf][bt], base + BM * 128 + r * 128 + ((u ^ (r & 7)) << 4));
            }
        };

        ldfrag(0, 0);
#pragma unroll
        for (int ks = 0; ks < 4; ks++) {
            const int cur = ks & 1;
            if (ks < 3) ldfrag(cur ^ 1, ks + 1);   // prefetch next fragments
#pragma unroll
            for (int mt = 0; mt < MT; mt++)
#pragma unroll
                for (int nt = 0; nt < NTT; nt++) {
                    const uint32_t b0 = (nt & 1) ? b[cur][nt >> 1][1] : b[cur][nt >> 1][0];
                    const uint32_t b1 = (nt & 1) ? b[cur][nt >> 1][3] : b[cur][nt >> 1][2];
                    mma_f16(acc[mt][nt], a[cur][mt], b0, b1);
                }
        }
    }

    const int crow = mBase + wm * (BM / 2) + (lane >> 2);
    const int ccol = nBase + wn * (BN / 4) + (lane & 3) * 2;
#pragma unroll
    for (int mt = 0; mt < MT; mt++)
#pragma unroll
        for (int nt = 0; nt < NTT; nt++) {
            float* p0 = C + (size_t)(crow + mt * 16) * DIM + ccol + nt * 8;
            float* p1 = p0 + 8 * DIM;
            *(float2*)p0 = make_float2(acc[mt][nt][0], acc[mt][nt][1]);
            *(float2*)p1 = make_float2(acc[mt][nt][2], acc[mt][nt][3]);
        }
}

// QKV: 384 CTAs (3 matrices x 32 m-tiles x 4 n-tiles), BM=64 BN=128.
__global__ void __launch_bounds__(256, 2)
qkv_gemm()
{
    const int j = blockIdx.x;
    const int which = j >> 7, t = j & 127;
    const __half* B = (which == 0) ? g_wqh : (which == 1) ? g_wkh : g_wvh;
    float*       C  = (which == 0) ? g_Q   : (which == 1) ? g_K   : g_V;
    gemm_tile<64, 128>(g_hh, B, C, (t >> 2) * 64, (t & 3) * 128, 8);
}

// out: 256 CTAs (32 m-tiles x 8 n-tiles), BM=64 BN=64.  Grid-limited to
// ~1.7 CTA/SM, so give ptxas the full register budget (occ cap 2).
__global__ void __launch_bounds__(256, 2)
out_gemm(float* __restrict__ out)
{
    const int t = blockIdx.x;
    gemm_tile<64, 64>(g_Oh, g_woh, out, (t >> 3) * 64, (t & 7) * 64, 8);
}

// ---------------- fp32 -> fp16 convert (vectorized) -------------------------
__global__ void __launch_bounds__(256)
split_kernel(const float* __restrict__ h,  const float* __restrict__ wq,
             const float* __restrict__ wk, const float* __restrict__ wv,
             const float* __restrict__ wo)
{
    const int i = blockIdx.x * 256 + threadIdx.x;   // vec4 index
    const float4* src; __half* dst; int off;
    if (i < 262144) { src = (const float4*)h; dst = g_hh; off = i; }
    else {
        const int j = i - 262144;
        const int w = j >> 16;
        off = j & 65535;
        src = (const float4*)((w == 0) ? wq : (w == 1) ? wk : (w == 2) ? wv : wo);
        dst = (w == 0) ? g_wqh : (w == 1) ? g_wkh : (w == 2) ? g_wvh : g_woh;
    }
    const float4 x = src[off];
    __half2* d = (__half2*)(dst + (size_t)off * 4);
    d[0] = __floats2half2_rn(x.x, x.y);
    d[1] = __floats2half2_rn(x.z, x.w);
}

// ---------------------------------------------------------------------------
// Fused moments + apply.  Block per token, 256 threads (8 warps).
// ---------------------------------------------------------------------------
__device__ __constant__ float c_invfact[NMOM] = {
    1.0f, 1.0f, 0.5f, 1.6666667e-1f, 4.1666668e-2f, 8.3333338e-3f,
    1.3888889e-3f, 1.9841270e-4f, 2.4801588e-5f, 2.7557319e-6f,
    2.7557319e-7f, 2.5052108e-8f, 2.0876757e-9f };

__global__ void __launch_bounds__(256)
ma_kernel()
{
    const int n    = blockIdx.x;
    const int tid  = threadIdx.x;
    const int lane = tid & 31, w = tid >> 5;

    __shared__ float sp[NCOEF][256];
    __shared__ float sc[NCOEF];

    const float* kp = g_K + (size_t)n * DIM;
    const float* vp = g_V + (size_t)n * DIM;

    const float k0 = kp[tid], k1 = kp[tid + 256];
    const float v0 = vp[tid], v1 = vp[tid + 256];

    {
        float p0 = 1.f, p1 = 1.f;
#pragma unroll
        for (int j = 0; j < NMOM; j++) {
            sp[NMOM + j][tid] = p0 + p1;
            sp[j][tid]        = fmaf(p0, v0, p1 * v1);
            p0 *= k0; p1 *= k1;
        }
    }
    __syncthreads();

#pragma unroll
    for (int cc = 0; cc < 4; cc++) {
        const int c = w + cc * 8;
        if (c < NCOEF) {
            float s = 0.f;
#pragma unroll
            for (int q = 0; q < 8; q++) s += sp[c][lane + q * 32];
#pragma unroll
            for (int off = 16; off > 0; off >>= 1)
                s += __shfl_xor_sync(0xFFFFFFFFu, s, off);
            if (lane == 0)
                sc[c] = s * c_invfact[(c < NMOM) ? c : c - NMOM];
        }
    }
    __syncthreads();

    const float* qrow = g_Q + (size_t)n * DIM;
    float c[2], nu[2], de[2];
#pragma unroll
    for (int t = 0; t < 2; t++) {
        c[t]  = qrow[tid + t * 256] * 0.04419417382415922f;
        nu[t] = sc[NMOM - 1];
        de[t] = sc[NCOEF - 1];
    }
#pragma unroll
    for (int j = NMOM - 2; j >= 0; j--) {
        const float cu = sc[j], cd = sc[NMOM + j];
#pragma unroll
        for (int t = 0; t < 2; t++) {
            nu[t] = fmaf(nu[t], c[t], cu);
            de[t] = fmaf(de[t], c[t], cd);
        }
    }
    __half* row = g_Oh + (size_t)n * DIM;
#pragma unroll
    for (int t = 0; t < 2; t++)
        row[tid + t * 256] = __float2half_rn(nu[t] / de[t]);
}

// ---------------------------------------------------------------------------
extern "C" void kernel_launch(void* const* d_in, const int* in_sizes, int n_in,
                              void* d_out, int out_size)
{
    const float* h  = (const float*)d_in[0];
    const float* wq = (const float*)d_in[1];
    const float* wk = (const float*)d_in[2];
    const float* wv = (const float*)d_in[3];
    const float* wo = (const float*)d_in[4];
    float* out = (float*)d_out;

    static int attr_done = 0;
    if (!attr_done) {
        cudaFuncSetAttribute(qkv_gemm, cudaFuncAttributeMaxDynamicSharedMemorySize, 98304);
        cudaFuncSetAttribute(out_gemm, cudaFuncAttributeMaxDynamicSharedMemorySize, 65536);
        attr_done = 1;
    }

    split_kernel<<<2048, 256>>>(h, wq, wk, wv, wo);
    qkv_gemm<<<384, 256, 98304>>>();
    ma_kernel<<<NTOK, 256>>>();
    out_gemm<<<256, 256, 65536>>>(out);
}

// round 12
// speedup vs baseline: 5.8447x; 1.0082x over previous
#include <cuda_runtime.h>
#include <cuda_fp16.h>
#include <cstdint>

#define NTOK 2048
#define DIM  512
#define NMOM 13
#define NCOEF (2*NMOM)

// ---------------- scratch (device globals: allocation-free) ----------------
__device__ __half g_hh [NTOK*DIM];
__device__ __half g_Oh [NTOK*DIM];
__device__ __half g_wqh[DIM*DIM];
__device__ __half g_wkh[DIM*DIM];
__device__ __half g_wvh[DIM*DIM];
__device__ __half g_woh[DIM*DIM];
__device__ float g_Q[NTOK*DIM], g_K[NTOK*DIM], g_V[NTOK*DIM];

// ---------------- PTX helpers ----------------
__device__ __forceinline__ uint32_t smem_u32(const void* p) {
    uint32_t a;
    asm("{ .reg .u64 t; cvta.to.shared.u64 t, %1; cvt.u32.u64 %0, t; }" : "=r"(a) : "l"(p));
    return a;
}
__device__ __forceinline__ void cpa16(uint32_t sdst, const void* gsrc) {
    asm volatile("cp.async.cg.shared.global [%0], [%1], 16;\n" :: "r"(sdst), "l"(gsrc));
}
#define CP_COMMIT() asm volatile("cp.async.commit_group;\n" ::: "memory")
#define CP_WAIT(n)  asm volatile("cp.async.wait_group %0;\n" :: "n"(n) : "memory")

__device__ __forceinline__ void ldsm4(uint32_t* r, uint32_t addr) {
    asm volatile("ldmatrix.sync.aligned.m8n8.x4.shared.b16 {%0,%1,%2,%3}, [%4];"
        : "=r"(r[0]), "=r"(r[1]), "=r"(r[2]), "=r"(r[3]) : "r"(addr));
}
__device__ __forceinline__ void mma_f16(float* c, const uint32_t* a,
                                        uint32_t b0, uint32_t b1) {
    asm volatile(
        "mma.sync.aligned.m16n8k16.row.col.f32.f16.f16.f32 "
        "{%0,%1,%2,%3}, {%4,%5,%6,%7}, {%8,%9}, {%0,%1,%2,%3};"
        : "+f"(c[0]), "+f"(c[1]), "+f"(c[2]), "+f"(c[3])
        : "r"(a[0]), "r"(a[1]), "r"(a[2]), "r"(a[3]), "r"(b0), "r"(b1));
}

// ---------------------------------------------------------------------------
// fp16 GEMM tile, 3-stage cp.async pipeline.  C[m,n] = sum_k A[m,k]*B[n,k].
// BM in {32,64}, BN in {64,128}; 256 threads, warps 2(m) x 4(n); K=kIters*64.
// ---------------------------------------------------------------------------
template<int BM, int BN>
__device__ __forceinline__ void gemm_fill(uint32_t base,
    const __half* A, const __half* B, int k0, int tid)
{
#pragma unroll
    for (int i = 0; i < BM / 32; i++) {
        const int idx = i * 256 + tid;
        const int r = idx >> 3, u = idx & 7;
        cpa16(base + r * 128 + ((u ^ (r & 7)) << 4),
              A + (size_t)r * DIM + k0 + u * 8);
    }
#pragma unroll
    for (int i = 0; i < BN / 32; i++) {
        const int idx = i * 256 + tid;
        const int r = idx >> 3, u = idx & 7;
        cpa16(base + BM * 128 + r * 128 + ((u ^ (r & 7)) << 4),
              B + (size_t)r * DIM + k0 + u * 8);
    }
}

template<int BM, int BN>
__device__ void gemm_tile(const __half* __restrict__ A,
                          const __half* __restrict__ B,
                          float* __restrict__ C,
                          int mBase, int nBase, int kIters)
{
    constexpr int MT  = BM / 32;
    constexpr int BT  = BN / 64;
    constexpr int NTT = BN / 32;
    constexpr int STG = (BM + BN) * 128;

    extern __shared__ __align__(1024) char smem[];
    const uint32_t sb = smem_u32(smem);
    const int tid = threadIdx.x, lane = tid & 31, wid = tid >> 5;
    const int wm = wid >> 2, wn = wid & 3;

    const __half* Ab = A + (size_t)mBase * DIM;
    const __half* Bb = B + (size_t)nBase * DIM;

    float acc[MT][NTT][4];
#pragma unroll
    for (int i = 0; i < MT; i++)
#pragma unroll
        for (int j = 0; j < NTT; j++)
#pragma unroll
            for (int q = 0; q < 4; q++) acc[i][j][q] = 0.f;

    // Prologue: fill stages 0..1 (2 committed groups in flight).
#pragma unroll
    for (int s = 0; s < 2; s++) {
        gemm_fill<BM, BN>(sb + s * STG, Ab, Bb, s * 64, tid);
        CP_COMMIT();
    }

    const int lrow = lane & 15, lhi = lane >> 4;

    int stage = 0, fstage = 2;
    for (int it = 0; it < kIters; ++it) {
        CP_WAIT(1);               // fill(it) complete; 1 younger group in flight
        __syncthreads();
        if (it + 2 < kIters)      // refill stage (it+2)%3 (consumed at it-1)
            gemm_fill<BM, BN>(sb + fstage * STG, Ab, Bb, (it + 2) * 64, tid);
        CP_COMMIT();              // possibly-empty group keeps wait count honest

        const uint32_t base = sb + stage * STG;
#pragma unroll
        for (int ks = 0; ks < 4; ks++) {
            const int u = ks * 2 + lhi;
            uint32_t a[MT][4], b[BT][4];
#pragma unroll
            for (int mt = 0; mt < MT; mt++) {
                const int r = wm * (BM / 2) + mt * 16 + lrow;
                ldsm4(a[mt], base + r * 128 + ((u ^ (r & 7)) << 4));
            }
#pragma unroll
            for (int bt = 0; bt < BT; bt++) {
                const int r = wn * (BN / 4) + bt * 16 + lrow;
                ldsm4(b[bt], base + BM * 128 + r * 128 + ((u ^ (r & 7)) << 4));
            }
#pragma unroll
            for (int mt = 0; mt < MT; mt++)
#pragma unroll
                for (int nt = 0; nt < NTT; nt++) {
                    const uint32_t b0 = (nt & 1) ? b[nt >> 1][1] : b[nt >> 1][0];
                    const uint32_t b1 = (nt & 1) ? b[nt >> 1][3] : b[nt >> 1][2];
                    mma_f16(acc[mt][nt], a[mt], b0, b1);
                }
        }
        stage  = (stage  == 2) ? 0 : stage + 1;
        fstage = (fstage == 2) ? 0 : fstage + 1;
    }

    const int crow = mBase + wm * (BM / 2) + (lane >> 2);
    const int ccol = nBase + wn * (BN / 4) + (lane & 3) * 2;
#pragma unroll
    for (int mt = 0; mt < MT; mt++)
#pragma unroll
        for (int nt = 0; nt < NTT; nt++) {
            float* p0 = C + (size_t)(crow + mt * 16) * DIM + ccol + nt * 8;
            float* p1 = p0 + 8 * DIM;
            *(float2*)p0 = make_float2(acc[mt][nt][0], acc[mt][nt][1]);
            *(float2*)p1 = make_float2(acc[mt][nt][2], acc[mt][nt][3]);
        }
}

// QKV: 384 CTAs (3 matrices x 32 m-tiles x 4 n-tiles), BM=64 BN=128,
// 3-stage (72KB) -> occ 3 -> whole grid resident in one wave.
__global__ void __launch_bounds__(256, 3)
qkv_gemm()
{
    const int j = blockIdx.x;
    const int which = j >> 7, t = j & 127;
    const __half* B = (which == 0) ? g_wqh : (which == 1) ? g_wkh : g_wvh;
    float*       C  = (which == 0) ? g_Q   : (which == 1) ? g_K   : g_V;
    gemm_tile<64, 128>(g_hh, B, C, (t >> 2) * 64, (t & 3) * 128, 8);
}

// out: 512 CTAs (64 m-tiles x 8 n-tiles), BM=32 BN=64, 3-stage (36KB).
__global__ void __launch_bounds__(256, 4)
out_gemm(float* __restrict__ out)
{
    const int t = blockIdx.x;
    gemm_tile<32, 64>(g_Oh, g_woh, out, (t >> 3) * 32, (t & 7) * 64, 8);
}

// ---------------- fp32 -> fp16 convert (vectorized) -------------------------
__global__ void __launch_bounds__(256)
split_kernel(const float* __restrict__ h,  const float* __restrict__ wq,
             const float* __restrict__ wk, const float* __restrict__ wv,
             const float* __restrict__ wo)
{
    const int i = blockIdx.x * 256 + threadIdx.x;   // vec4 index
    const float4* src; __half* dst; int off;
    if (i < 262144) { src = (const float4*)h; dst = g_hh; off = i; }
    else {
        const int j = i - 262144;
        const int w = j >> 16;
        off = j & 65535;
        src = (const float4*)((w == 0) ? wq : (w == 1) ? wk : (w == 2) ? wv : wo);
        dst = (w == 0) ? g_wqh : (w == 1) ? g_wkh : (w == 2) ? g_wvh : g_woh;
    }
    const float4 x = src[off];
    __half2* d = (__half2*)(dst + (size_t)off * 4);
    d[0] = __floats2half2_rn(x.x, x.y);
    d[1] = __floats2half2_rn(x.z, x.w);
}

// ---------------------------------------------------------------------------
// Fused moments + apply.  Block per token, 256 threads (8 warps).
// ---------------------------------------------------------------------------
__device__ __constant__ float c_invfact[NMOM] = {
    1.0f, 1.0f, 0.5f, 1.6666667e-1f, 4.1666668e-2f, 8.3333338e-3f,
    1.3888889e-3f, 1.9841270e-4f, 2.4801588e-5f, 2.7557319e-6f,
    2.7557319e-7f, 2.5052108e-8f, 2.0876757e-9f };

__global__ void __launch_bounds__(256)
ma_kernel()
{
    const int n    = blockIdx.x;
    const int tid  = threadIdx.x;
    const int lane = tid & 31, w = tid >> 5;

    __shared__ float sp[NCOEF][256];
    __shared__ float sc[NCOEF];

    const float* kp = g_K + (size_t)n * DIM;
    const float* vp = g_V + (size_t)n * DIM;

    const float k0 = kp[tid], k1 = kp[tid + 256];
    const float v0 = vp[tid], v1 = vp[tid + 256];

    {
        float p0 = 1.f, p1 = 1.f;
#pragma unroll
        for (int j = 0; j < NMOM; j++) {
            sp[NMOM + j][tid] = p0 + p1;
            sp[j][tid]        = fmaf(p0, v0, p1 * v1);
            p0 *= k0; p1 *= k1;
        }
    }
    __syncthreads();

#pragma unroll
    for (int cc = 0; cc < 4; cc++) {
        const int c = w + cc * 8;
        if (c < NCOEF) {
            float s = 0.f;
#pragma unroll
            for (int q = 0; q < 8; q++) s += sp[c][lane + q * 32];
#pragma unroll
            for (int off = 16; off > 0; off >>= 1)
                s += __shfl_xor_sync(0xFFFFFFFFu, s, off);
            if (lane == 0)
                sc[c] = s * c_invfact[(c < NMOM) ? c : c - NMOM];
        }
    }
    __syncthreads();

    const float* qrow = g_Q + (size_t)n * DIM;
    float c[2], nu[2], de[2];
#pragma unroll
    for (int t = 0; t < 2; t++) {
        c[t]  = qrow[tid + t * 256] * 0.04419417382415922f;
        nu[t] = sc[NMOM - 1];
        de[t] = sc[NCOEF - 1];
    }
#pragma unroll
    for (int j = NMOM - 2; j >= 0; j--) {
        const float cu = sc[j], cd = sc[NMOM + j];
#pragma unroll
        for (int t = 0; t < 2; t++) {
            nu[t] = fmaf(nu[t], c[t], cu);
            de[t] = fmaf(de[t], c[t], cd);
        }
    }
    __half* row = g_Oh + (size_t)n * DIM;
#pragma unroll
    for (int t = 0; t < 2; t++)
        row[tid + t * 256] = __float2half_rn(nu[t] / de[t]);
}

// ---------------------------------------------------------------------------
extern "C" void kernel_launch(void* const* d_in, const int* in_sizes, int n_in,
                              void* d_out, int out_size)
{
    const float* h  = (const float*)d_in[0];
    const float* wq = (const float*)d_in[1];
    const float* wk = (const float*)d_in[2];
    const float* wv = (const float*)d_in[3];
    const float* wo = (const float*)d_in[4];
    float* out = (float*)d_out;

    static int attr_done = 0;
    if (!attr_done) {
        cudaFuncSetAttribute(qkv_gemm, cudaFuncAttributeMaxDynamicSharedMemorySize, 73728);
        cudaFuncSetAttribute(out_gemm, cudaFuncAttributeMaxDynamicSharedMemorySize, 36864);
        attr_done = 1;
    }

    split_kernel<<<2048, 256>>>(h, wq, wk, wv, wo);
    qkv_gemm<<<384, 256, 73728>>>();
    ma_kernel<<<NTOK, 256>>>();
    out_gemm<<<512, 256, 36864>>>(out);
}